// round 10
// baseline (speedup 1.0000x reference)
#include <cuda_runtime.h>

#define TT 2048
#define BATCH 4

// fp16 packed-pair scratch (1 unsigned = 2 halves). Allocation is forbidden.
__device__ unsigned g_x[(size_t)BATCH * TT * 512];     // x fp16 [b,t,1024h]
__device__ unsigned g_wq[512 * 1024];                  // Wq*0.125 fp16
__device__ unsigned g_wkv[512 * 512];                  // [Wk rows 0..255 | Wv rows 256..511]
__device__ unsigned g_wp[512 * 1024];
__device__ unsigned g_q[(size_t)BATCH * TT * 512];     // q fp16 (pre-scaled)
__device__ unsigned g_kv[(size_t)BATCH * TT * 256];    // [b,t, k 128u | v 128u]
__device__ unsigned g_attn[(size_t)BATCH * TT * 512];

__device__ __forceinline__ unsigned sptr(const void* p) {
    return (unsigned)__cvta_generic_to_shared(p);
}

__device__ __forceinline__ unsigned pack_h2(float lo, float hi) {
    unsigned r;
    asm("cvt.rn.f16x2.f32 %0, %1, %2;" : "=r"(r) : "f"(hi), "f"(lo));
    return r;
}

__device__ __forceinline__ void cpa16(unsigned daddr, const void* src) {
    asm volatile("cp.async.cg.shared.global [%0], [%1], 16;" :: "r"(daddr), "l"(src));
}
__device__ __forceinline__ void cpcommit() {
    asm volatile("cp.async.commit_group;");
}
__device__ __forceinline__ void cpwait0() {
    asm volatile("cp.async.wait_group 0;");
}
__device__ __forceinline__ void cpwait1() {
    asm volatile("cp.async.wait_group 1;");
}
__device__ __forceinline__ void cpwait2() {
    asm volatile("cp.async.wait_group 2;");
}

__device__ __forceinline__ void ldsm4(unsigned& r0, unsigned& r1, unsigned& r2, unsigned& r3, unsigned a) {
    asm volatile("ldmatrix.sync.aligned.m8n8.x4.shared.b16 {%0,%1,%2,%3},[%4];"
                 : "=r"(r0), "=r"(r1), "=r"(r2), "=r"(r3) : "r"(a));
}

__device__ __forceinline__ void ldsm4t(unsigned& r0, unsigned& r1, unsigned& r2, unsigned& r3, unsigned a) {
    asm volatile("ldmatrix.sync.aligned.m8n8.x4.trans.shared.b16 {%0,%1,%2,%3},[%4];"
                 : "=r"(r0), "=r"(r1), "=r"(r2), "=r"(r3) : "r"(a));
}

__device__ __forceinline__ void mma16(float* d,
                                      unsigned a0, unsigned a1, unsigned a2, unsigned a3,
                                      unsigned b0, unsigned b1) {
    asm volatile("mma.sync.aligned.m16n8k16.row.col.f32.f16.f16.f32 "
                 "{%0,%1,%2,%3},{%4,%5,%6,%7},{%8,%9},{%0,%1,%2,%3};"
                 : "+f"(d[0]), "+f"(d[1]), "+f"(d[2]), "+f"(d[3])
                 : "r"(a0), "r"(a1), "r"(a2), "r"(a3), "r"(b0), "r"(b1));
}

// ---------------------------------------------------------------------------
// fp32 -> fp16 pair conversion (with scale), vectorized by 4 floats.
// ---------------------------------------------------------------------------
__global__ __launch_bounds__(256) void conv_f2h(
    const float* __restrict__ in, unsigned* __restrict__ out, int n4, float scale)
{
    int i = blockIdx.x * 256 + threadIdx.x;
    if (i < n4) {
        float4 f = ((const float4*)in)[i];
        uint2 u;
        u.x = pack_h2(f.x * scale, f.y * scale);
        u.y = pack_h2(f.z * scale, f.w * scale);
        ((uint2*)out)[i] = u;
    }
}

// ---------------------------------------------------------------------------
// Stage one BK=64 slab of A and B (128 rows each) with 128 threads.
// Each thread: one A row + one B row, 8 x 16B cp.async each.
// ---------------------------------------------------------------------------
__device__ __forceinline__ void gemm_stage128(
    unsigned sAb, unsigned sBb,
    const unsigned* __restrict__ Ap, const unsigned* __restrict__ Bp,
    int m0, int n0, int k0u, int tid)
{
    int row = tid;
    int rx = row % 8;
    const unsigned* asrc = Ap + (m0 + row) * 512 + k0u;
    const unsigned* bsrc = Bp + (n0 + row) * 512 + k0u;
    unsigned abase = sAb + row * 128;
    unsigned bbase = sBb + row * 128;
    for (int grp = 0; grp < 8; grp++) {
        unsigned sw = (unsigned)((grp ^ rx) * 16);
        cpa16(abase + sw, asrc + grp * 4);
        cpa16(bbase + sw, bsrc + grp * 4);
    }
}

// ---------------------------------------------------------------------------
// GEMM fp16 out: block 128x128, 4 warps (warp tile 64x64), 3-stage cp.async.
// ---------------------------------------------------------------------------
__global__ __launch_bounds__(128) void gemm_hh_h(
    const unsigned* __restrict__ Ap, const unsigned* __restrict__ Bp,
    unsigned* __restrict__ Cp, int Nu)
{
    __shared__ unsigned As[3][128 * 32];
    __shared__ unsigned Bs[3][128 * 32];
    unsigned sA[3];
    unsigned sB[3];
    sA[0] = sptr(As[0]); sA[1] = sptr(As[1]); sA[2] = sptr(As[2]);
    sB[0] = sptr(Bs[0]); sB[1] = sptr(Bs[1]); sB[2] = sptr(Bs[2]);

    const int tid = threadIdx.x;
    const int lane = tid % 32;
    const int warp = tid / 32;
    const int gid = lane / 4;
    const int tig = lane % 4;
    const int wm = warp / 2;
    const int wn = warp % 2;
    const int m0 = blockIdx.y * 128;
    const int n0 = blockIdx.x * 128;

    const int arow = wm * 64 + (lane % 16);
    const int ga_add = lane / 16;
    const int brow = wn * 64 + ((lane / 16) % 2) * 8 + (lane % 8);
    const int gb_add = (lane / 8) % 2;

    float acc[4][8][4];
    for (int i = 0; i < 4; i++) {
        for (int j = 0; j < 8; j++) {
            for (int q = 0; q < 4; q++) { acc[i][j][q] = 0.f; }
        }
    }

    gemm_stage128(sA[0], sB[0], Ap, Bp, m0, n0, 0, tid);
    cpcommit();
    gemm_stage128(sA[1], sB[1], Ap, Bp, m0, n0, 32, tid);
    cpcommit();
    gemm_stage128(sA[2], sB[2], Ap, Bp, m0, n0, 64, tid);
    cpcommit();

    for (int kk = 0; kk < 16; kk++) {
        if (kk < 14) { cpwait2(); }
        else if (kk == 14) { cpwait1(); }
        else { cpwait0(); }
        __syncthreads();
        int buf = kk % 3;
        const unsigned cA = sA[buf];
        const unsigned cB = sB[buf];

        for (int ks = 0; ks < 4; ks++) {
            unsigned af[4][4];
            unsigned bf[4][4];
            for (int mt = 0; mt < 4; mt++) {
                int r = arow + mt * 16;
                int grp = (ks * 2 + ga_add) ^ (r % 8);
                ldsm4(af[mt][0], af[mt][1], af[mt][2], af[mt][3], cA + r * 128 + grp * 16);
            }
            for (int p = 0; p < 4; p++) {
                int r = brow + p * 16;
                int grp = (ks * 2 + gb_add) ^ (r % 8);
                ldsm4(bf[p][0], bf[p][1], bf[p][2], bf[p][3], cB + r * 128 + grp * 16);
            }
            for (int mt = 0; mt < 4; mt++) {
                for (int p = 0; p < 4; p++) {
                    mma16(acc[mt][2 * p + 0], af[mt][0], af[mt][1], af[mt][2], af[mt][3],
                          bf[p][0], bf[p][1]);
                    mma16(acc[mt][2 * p + 1], af[mt][0], af[mt][1], af[mt][2], af[mt][3],
                          bf[p][2], bf[p][3]);
                }
            }
        }
        __syncthreads();
        if (kk < 13) {
            gemm_stage128(sA[buf], sB[buf], Ap, Bp, m0, n0, (kk + 3) * 32, tid);
            cpcommit();
        }
    }

    for (int mt = 0; mt < 4; mt++) {
        for (int nt = 0; nt < 8; nt++) {
            int row = m0 + wm * 64 + mt * 16 + gid;
            int colu = (n0 + wn * 64 + nt * 8 + 2 * tig) / 2;
            Cp[row * Nu + colu] = pack_h2(acc[mt][nt][0], acc[mt][nt][1]);
            Cp[(row + 8) * Nu + colu] = pack_h2(acc[mt][nt][2], acc[mt][nt][3]);
        }
    }
}

// ---------------------------------------------------------------------------
// GEMM fp32 out + bias: same structure.
// ---------------------------------------------------------------------------
__global__ __launch_bounds__(128) void gemm_hh_f(
    const unsigned* __restrict__ Ap, const unsigned* __restrict__ Bp,
    float* __restrict__ Cp, const float* __restrict__ bias)
{
    __shared__ unsigned As[3][128 * 32];
    __shared__ unsigned Bs[3][128 * 32];
    unsigned sA[3];
    unsigned sB[3];
    sA[0] = sptr(As[0]); sA[1] = sptr(As[1]); sA[2] = sptr(As[2]);
    sB[0] = sptr(Bs[0]); sB[1] = sptr(Bs[1]); sB[2] = sptr(Bs[2]);

    const int tid = threadIdx.x;
    const int lane = tid % 32;
    const int warp = tid / 32;
    const int gid = lane / 4;
    const int tig = lane % 4;
    const int wm = warp / 2;
    const int wn = warp % 2;
    const int m0 = blockIdx.y * 128;
    const int n0 = blockIdx.x * 128;

    const int arow = wm * 64 + (lane % 16);
    const int ga_add = lane / 16;
    const int brow = wn * 64 + ((lane / 16) % 2) * 8 + (lane % 8);
    const int gb_add = (lane / 8) % 2;

    float acc[4][8][4];
    for (int i = 0; i < 4; i++) {
        for (int j = 0; j < 8; j++) {
            for (int q = 0; q < 4; q++) { acc[i][j][q] = 0.f; }
        }
    }

    gemm_stage128(sA[0], sB[0], Ap, Bp, m0, n0, 0, tid);
    cpcommit();
    gemm_stage128(sA[1], sB[1], Ap, Bp, m0, n0, 32, tid);
    cpcommit();
    gemm_stage128(sA[2], sB[2], Ap, Bp, m0, n0, 64, tid);
    cpcommit();

    for (int kk = 0; kk < 16; kk++) {
        if (kk < 14) { cpwait2(); }
        else if (kk == 14) { cpwait1(); }
        else { cpwait0(); }
        __syncthreads();
        int buf = kk % 3;
        const unsigned cA = sA[buf];
        const unsigned cB = sB[buf];

        for (int ks = 0; ks < 4; ks++) {
            unsigned af[4][4];
            unsigned bf[4][4];
            for (int mt = 0; mt < 4; mt++) {
                int r = arow + mt * 16;
                int grp = (ks * 2 + ga_add) ^ (r % 8);
                ldsm4(af[mt][0], af[mt][1], af[mt][2], af[mt][3], cA + r * 128 + grp * 16);
            }
            for (int p = 0; p < 4; p++) {
                int r = brow + p * 16;
                int grp = (ks * 2 + gb_add) ^ (r % 8);
                ldsm4(bf[p][0], bf[p][1], bf[p][2], bf[p][3], cB + r * 128 + grp * 16);
            }
            for (int mt = 0; mt < 4; mt++) {
                for (int p = 0; p < 4; p++) {
                    mma16(acc[mt][2 * p + 0], af[mt][0], af[mt][1], af[mt][2], af[mt][3],
                          bf[p][0], bf[p][1]);
                    mma16(acc[mt][2 * p + 1], af[mt][0], af[mt][1], af[mt][2], af[mt][3],
                          bf[p][2], bf[p][3]);
                }
            }
        }
        __syncthreads();
        if (kk < 13) {
            gemm_stage128(sA[buf], sB[buf], Ap, Bp, m0, n0, (kk + 3) * 32, tid);
            cpcommit();
        }
    }

    for (int mt = 0; mt < 4; mt++) {
        for (int nt = 0; nt < 8; nt++) {
            int row = m0 + wm * 64 + mt * 16 + gid;
            int col = n0 + wn * 64 + nt * 8 + 2 * tig;
            float bb0 = bias[col];
            float bb1 = bias[col + 1];
            *(float2*)(Cp + row * 1024 + col) =
                make_float2(acc[mt][nt][0] + bb0, acc[mt][nt][1] + bb1);
            *(float2*)(Cp + (row + 8) * 1024 + col) =
                make_float2(acc[mt][nt][2] + bb0, acc[mt][nt][3] + bb1);
        }
    }
}

// ---------------------------------------------------------------------------
// Flash attention: Br=128, 4 warps, 2-stage cp.async K/V pipeline (unchanged).
// ---------------------------------------------------------------------------
__device__ __forceinline__ void kv_stage(
    unsigned sKb, unsigned sVb, const unsigned* __restrict__ kvrow0, int kt, int tid)
{
    int r = tid / 2;
    int rx = r % 8;
    const unsigned* src = kvrow0 + (kt * 64 + r) * 256;
    for (int j = 0; j < 4; j++) {
        int grp = j * 2 + (tid % 2);
        unsigned sw = (unsigned)((grp ^ rx) * 16);
        cpa16(sKb + r * 128 + sw, src + grp * 4);
        cpa16(sVb + r * 128 + sw, src + 128 + grp * 4);
    }
}

__global__ __launch_bounds__(128) void attn_h(
    const unsigned* __restrict__ qbuf, const unsigned* __restrict__ kvbuf,
    unsigned* __restrict__ obuf)
{
    __shared__ unsigned Qs[128 * 32];
    __shared__ unsigned Ks[2][64 * 32];
    __shared__ unsigned Vs[2][64 * 32];
    const unsigned sQ = sptr(Qs);
    unsigned sK[2];
    unsigned sV[2];
    sK[0] = sptr(Ks[0]); sK[1] = sptr(Ks[1]);
    sV[0] = sptr(Vs[0]); sV[1] = sptr(Vs[1]);

    const int tid = threadIdx.x;
    const int lane = tid % 32;
    const int warp = tid / 32;
    const int gid = lane / 4;
    const int tig = lane % 4;
    const int q0 = blockIdx.x * 128;
    const int bh = blockIdx.y;
    const int bb = bh / 16;
    const int hh = bh % 16;
    const int gg = hh / 4;

    const int kmax = q0 / 64 + 1;
    const unsigned* kvrow0 = kvbuf + (size_t)bb * TT * 256 + gg * 32;

    kv_stage(sK[0], sV[0], kvrow0, 0, tid);
    cpcommit();
    kv_stage(sK[1], sV[1], kvrow0, 1, tid);
    cpcommit();

    {
        const unsigned* srow = qbuf + (bb * TT + q0 + tid) * 512 + hh * 32;
        unsigned* drow = Qs + tid * 32;
        int rx = tid % 8;
        for (int grp = 0; grp < 8; grp++) {
            *(uint4*)(drow + (grp ^ rx) * 4) = *(const uint4*)(srow + grp * 4);
        }
    }
    __syncthreads();

    unsigned qf[2][4][4];
    const int qga = lane / 16;
    for (int mt = 0; mt < 2; mt++) {
        int qrow = warp * 32 + mt * 16 + (lane % 16);
        for (int ks = 0; ks < 4; ks++) {
            int grp = (ks * 2 + qga) ^ (qrow % 8);
            ldsm4(qf[mt][ks][0], qf[mt][ks][1], qf[mt][ks][2], qf[mt][ks][3],
                  sQ + qrow * 128 + grp * 16);
        }
    }

    float oacc[2][8][4];
    for (int mt = 0; mt < 2; mt++) {
        for (int nt = 0; nt < 8; nt++) {
            for (int q = 0; q < 4; q++) { oacc[mt][nt][q] = 0.f; }
        }
    }
    float mr[2][2];
    float lr[2][2];
    for (int mt = 0; mt < 2; mt++) {
        mr[mt][0] = -1e30f; mr[mt][1] = -1e30f;
        lr[mt][0] = 0.f; lr[mt][1] = 0.f;
    }

    const int rw0 = q0 + warp * 32;

    const int s_nadd = ((lane / 16) % 2) * 8 + (lane % 8);
    const int s_gadd = (lane / 8) % 2;
    const int v_kadd = ((lane / 8) % 2) * 8 + (lane % 8);
    const int v_gadd = (lane / 16) % 2;

    for (int kt = 0; kt <= kmax; kt++) {
        if (kt < kmax) { cpwait1(); } else { cpwait0(); }
        __syncthreads();
        const unsigned cK = sK[kt % 2];
        const unsigned cV = sV[kt % 2];

        if (kt * 64 <= rw0 + 31) {
            float sc[2][8][4];
            for (int mt = 0; mt < 2; mt++) {
                for (int nt = 0; nt < 8; nt++) {
                    for (int q = 0; q < 4; q++) { sc[mt][nt][q] = 0.f; }
                }
            }
            for (int ks = 0; ks < 4; ks++) {
                for (int p = 0; p < 4; p++) {
                    int nrow = p * 16 + s_nadd;
                    int grp = (ks * 2 + s_gadd) ^ (nrow % 8);
                    unsigned kf0, kf1, kf2, kf3;
                    ldsm4(kf0, kf1, kf2, kf3, cK + nrow * 128 + grp * 16);
                    for (int mt = 0; mt < 2; mt++) {
                        mma16(sc[mt][2 * p + 0], qf[mt][ks][0], qf[mt][ks][1], qf[mt][ks][2], qf[mt][ks][3], kf0, kf1);
                        mma16(sc[mt][2 * p + 1], qf[mt][ks][0], qf[mt][ks][1], qf[mt][ks][2], qf[mt][ks][3], kf2, kf3);
                    }
                }
            }

            if (kt * 64 + 63 > rw0) {
                for (int mt = 0; mt < 2; mt++) {
                    int rowA = rw0 + mt * 16 + gid;
                    int rowB = rowA + 8;
                    for (int nt = 0; nt < 8; nt++) {
                        int kcol = kt * 64 + nt * 8 + 2 * tig;
                        if (kcol > rowA) { sc[mt][nt][0] = -1e30f; }
                        if (kcol + 1 > rowA) { sc[mt][nt][1] = -1e30f; }
                        if (kcol > rowB) { sc[mt][nt][2] = -1e30f; }
                        if (kcol + 1 > rowB) { sc[mt][nt][3] = -1e30f; }
                    }
                }
            }

            for (int mt = 0; mt < 2; mt++) {
                float mt0 = -1e30f;
                float mt1 = -1e30f;
                for (int nt = 0; nt < 8; nt++) {
                    mt0 = fmaxf(mt0, fmaxf(sc[mt][nt][0], sc[mt][nt][1]));
                    mt1 = fmaxf(mt1, fmaxf(sc[mt][nt][2], sc[mt][nt][3]));
                }
                mt0 = fmaxf(mt0, __shfl_xor_sync(0xffffffffu, mt0, 1));
                mt0 = fmaxf(mt0, __shfl_xor_sync(0xffffffffu, mt0, 2));
                mt1 = fmaxf(mt1, __shfl_xor_sync(0xffffffffu, mt1, 1));
                mt1 = fmaxf(mt1, __shfl_xor_sync(0xffffffffu, mt1, 2));
                float mn0 = fmaxf(mr[mt][0], mt0);
                float mn1 = fmaxf(mr[mt][1], mt1);
                float c0 = __expf(mr[mt][0] - mn0);
                float c1 = __expf(mr[mt][1] - mn1);
                float ps0 = 0.f;
                float ps1 = 0.f;
                for (int nt = 0; nt < 8; nt++) {
                    sc[mt][nt][0] = __expf(sc[mt][nt][0] - mn0);
                    sc[mt][nt][1] = __expf(sc[mt][nt][1] - mn0);
                    sc[mt][nt][2] = __expf(sc[mt][nt][2] - mn1);
                    sc[mt][nt][3] = __expf(sc[mt][nt][3] - mn1);
                    ps0 += sc[mt][nt][0] + sc[mt][nt][1];
                    ps1 += sc[mt][nt][2] + sc[mt][nt][3];
                    oacc[mt][nt][0] *= c0;
                    oacc[mt][nt][1] *= c0;
                    oacc[mt][nt][2] *= c1;
                    oacc[mt][nt][3] *= c1;
                }
                ps0 += __shfl_xor_sync(0xffffffffu, ps0, 1);
                ps0 += __shfl_xor_sync(0xffffffffu, ps0, 2);
                ps1 += __shfl_xor_sync(0xffffffffu, ps1, 1);
                ps1 += __shfl_xor_sync(0xffffffffu, ps1, 2);
                lr[mt][0] = lr[mt][0] * c0 + ps0;
                lr[mt][1] = lr[mt][1] * c1 + ps1;
                mr[mt][0] = mn0;
                mr[mt][1] = mn1;
            }

            for (int ks = 0; ks < 4; ks++) {
                unsigned pf[2][4];
                for (int mt = 0; mt < 2; mt++) {
                    pf[mt][0] = pack_h2(sc[mt][2 * ks + 0][0], sc[mt][2 * ks + 0][1]);
                    pf[mt][1] = pack_h2(sc[mt][2 * ks + 0][2], sc[mt][2 * ks + 0][3]);
                    pf[mt][2] = pack_h2(sc[mt][2 * ks + 1][0], sc[mt][2 * ks + 1][1]);
                    pf[mt][3] = pack_h2(sc[mt][2 * ks + 1][2], sc[mt][2 * ks + 1][3]);
                }
                for (int p = 0; p < 4; p++) {
                    int krow = ks * 16 + v_kadd;
                    int grp = (p * 2 + v_gadd) ^ (krow % 8);
                    unsigned vf0, vf1, vf2, vf3;
                    ldsm4t(vf0, vf1, vf2, vf3, cV + krow * 128 + grp * 16);
                    for (int mt = 0; mt < 2; mt++) {
                        mma16(oacc[mt][2 * p + 0], pf[mt][0], pf[mt][1], pf[mt][2], pf[mt][3], vf0, vf1);
                        mma16(oacc[mt][2 * p + 1], pf[mt][0], pf[mt][1], pf[mt][2], pf[mt][3], vf2, vf3);
                    }
                }
            }
        }

        __syncthreads();
        if (kt + 2 <= kmax) {
            kv_stage(sK[kt % 2], sV[kt % 2], kvrow0, kt + 2, tid);
            cpcommit();
        }
    }

    for (int mt = 0; mt < 2; mt++) {
        float i0 = 1.f / lr[mt][0];
        float i1 = 1.f / lr[mt][1];
        int rowA = rw0 + mt * 16 + gid;
        int rowB = rowA + 8;
        for (int nt = 0; nt < 8; nt++) {
            int colu = hh * 32 + nt * 4 + tig;
            obuf[(bb * TT + rowA) * 512 + colu] = pack_h2(oacc[mt][nt][0] * i0, oacc[mt][nt][1] * i0);
            obuf[(bb * TT + rowB) * 512 + colu] = pack_h2(oacc[mt][nt][2] * i1, oacc[mt][nt][3] * i1);
        }
    }
}

extern "C" void kernel_launch(void* const* d_in, const int* in_sizes, int n_in,
                              void* d_out, int out_size)
{
    const float* x  = (const float*)d_in[0];
    const float* Wq = (const float*)d_in[1];
    const float* Wk = (const float*)d_in[2];
    const float* Wv = (const float*)d_in[3];
    const float* Wp = (const float*)d_in[4];
    const float* bp = (const float*)d_in[5];
    float* out = (float*)d_out;

    unsigned* gx = 0;
    unsigned* gwq = 0;
    unsigned* gwkv = 0;
    unsigned* gwp = 0;
    unsigned* gq = 0;
    unsigned* gkv = 0;
    unsigned* ga = 0;
    cudaGetSymbolAddress((void**)&gx, g_x);
    cudaGetSymbolAddress((void**)&gwq, g_wq);
    cudaGetSymbolAddress((void**)&gwkv, g_wkv);
    cudaGetSymbolAddress((void**)&gwp, g_wp);
    cudaGetSymbolAddress((void**)&gq, g_q);
    cudaGetSymbolAddress((void**)&gkv, g_kv);
    cudaGetSymbolAddress((void**)&ga, g_attn);

    conv_f2h<<<8192, 256>>>(x, gx, 2097152, 1.f);
    conv_f2h<<<1024, 256>>>(Wq, gwq, 262144, 0.125f);
    conv_f2h<<<256, 256>>>(Wk, gwkv, 65536, 1.f);
    conv_f2h<<<256, 256>>>(Wv, gwkv + 256 * 512, 65536, 1.f);
    conv_f2h<<<1024, 256>>>(Wp, gwp, 262144, 1.f);

    gemm_hh_h<<<dim3(8, 64), 128>>>(gx, gwq, gq, 512);
    gemm_hh_h<<<dim3(4, 64), 128>>>(gx, gwkv, gkv, 256);

    attn_h<<<dim3(16, 64), 128>>>(gq, gkv, ga);

    gemm_hh_f<<<dim3(8, 64), 128>>>(ga, gwp, out, bp);
}

// round 11
// speedup vs baseline: 1.2754x; 1.2754x over previous
#include <cuda_runtime.h>

#define TT 2048
#define BATCH 4

// fp16 packed-pair scratch (1 unsigned = 2 halves). Allocation is forbidden.
__device__ unsigned g_x[(size_t)BATCH * TT * 512];     // x fp16 [b,t,1024h]
__device__ unsigned g_wq[512 * 1024];                  // Wq*0.125 fp16
__device__ unsigned g_wkv[512 * 512];                  // [Wk rows 0..255 | Wv rows 256..511]
__device__ unsigned g_wp[512 * 1024];
__device__ unsigned g_q[(size_t)BATCH * TT * 512];     // q fp16 (pre-scaled)
__device__ unsigned g_kv[(size_t)BATCH * TT * 256];    // [b,t, k 128u | v 128u]
__device__ unsigned g_attn[(size_t)BATCH * TT * 512];

__device__ __forceinline__ unsigned sptr(const void* p) {
    return (unsigned)__cvta_generic_to_shared(p);
}

__device__ __forceinline__ unsigned pack_h2(float lo, float hi) {
    unsigned r;
    asm("cvt.rn.f16x2.f32 %0, %1, %2;" : "=r"(r) : "f"(hi), "f"(lo));
    return r;
}

__device__ __forceinline__ void cpa16(unsigned daddr, const void* src) {
    asm volatile("cp.async.cg.shared.global [%0], [%1], 16;" :: "r"(daddr), "l"(src));
}
__device__ __forceinline__ void cpcommit() {
    asm volatile("cp.async.commit_group;");
}
__device__ __forceinline__ void cpwait0() {
    asm volatile("cp.async.wait_group 0;");
}
__device__ __forceinline__ void cpwait1() {
    asm volatile("cp.async.wait_group 1;");
}
__device__ __forceinline__ void cpwait2() {
    asm volatile("cp.async.wait_group 2;");
}

__device__ __forceinline__ void ldsm4(unsigned& r0, unsigned& r1, unsigned& r2, unsigned& r3, unsigned a) {
    asm volatile("ldmatrix.sync.aligned.m8n8.x4.shared.b16 {%0,%1,%2,%3},[%4];"
                 : "=r"(r0), "=r"(r1), "=r"(r2), "=r"(r3) : "r"(a));
}

__device__ __forceinline__ void ldsm4t(unsigned& r0, unsigned& r1, unsigned& r2, unsigned& r3, unsigned a) {
    asm volatile("ldmatrix.sync.aligned.m8n8.x4.trans.shared.b16 {%0,%1,%2,%3},[%4];"
                 : "=r"(r0), "=r"(r1), "=r"(r2), "=r"(r3) : "r"(a));
}

__device__ __forceinline__ void mma16(float* d,
                                      unsigned a0, unsigned a1, unsigned a2, unsigned a3,
                                      unsigned b0, unsigned b1) {
    asm volatile("mma.sync.aligned.m16n8k16.row.col.f32.f16.f16.f32 "
                 "{%0,%1,%2,%3},{%4,%5,%6,%7},{%8,%9},{%0,%1,%2,%3};"
                 : "+f"(d[0]), "+f"(d[1]), "+f"(d[2]), "+f"(d[3])
                 : "r"(a0), "r"(a1), "r"(a2), "r"(a3), "r"(b0), "r"(b1));
}

// ---------------------------------------------------------------------------
// fp32 -> fp16 pair conversion (with scale), vectorized by 4 floats.
// ---------------------------------------------------------------------------
__global__ __launch_bounds__(256) void conv_f2h(
    const float* __restrict__ in, unsigned* __restrict__ out, int n4, float scale)
{
    int i = blockIdx.x * 256 + threadIdx.x;
    if (i < n4) {
        float4 f = ((const float4*)in)[i];
        uint2 u;
        u.x = pack_h2(f.x * scale, f.y * scale);
        u.y = pack_h2(f.z * scale, f.w * scale);
        ((uint2*)out)[i] = u;
    }
}

// ---------------------------------------------------------------------------
// Stage one BK=64 slab of A and B into swizzled shared (cp.async, 8x16B/thread,
// 256 threads).
// ---------------------------------------------------------------------------
__device__ __forceinline__ void gemm_stage(
    unsigned sAb, unsigned sBb,
    const unsigned* __restrict__ Ap, const unsigned* __restrict__ Bp,
    int m0, int n0, int k0u, int tid)
{
    int tr = tid / 4;
    int tg = (tid % 4) * 2;
    for (int i = 0; i < 2; i++) {
        int row = tr + i * 64;
        int rx = row % 8;
        for (int j = 0; j < 2; j++) {
            int grp = tg + j;
            cpa16(sAb + (row * 32 + (grp ^ rx) * 4) * 4, Ap + (m0 + row) * 512 + k0u + grp * 4);
            cpa16(sBb + (row * 32 + (grp ^ rx) * 4) * 4, Bp + (n0 + row) * 512 + k0u + grp * 4);
        }
    }
}

// ---------------------------------------------------------------------------
// GEMM fp16 out: C[M, 2*Nu h] = A[M,1024] @ B[N,1024]^T. 3-stage cp.async,
// 256 threads, 8 warps (warp tile 64x32).
// ---------------------------------------------------------------------------
__global__ __launch_bounds__(256) void gemm_hh_h(
    const unsigned* __restrict__ Ap, const unsigned* __restrict__ Bp,
    unsigned* __restrict__ Cp, int Nu)
{
    __shared__ unsigned As[3][128 * 32];
    __shared__ unsigned Bs[3][128 * 32];
    unsigned sA[3];
    unsigned sB[3];
    sA[0] = sptr(As[0]); sA[1] = sptr(As[1]); sA[2] = sptr(As[2]);
    sB[0] = sptr(Bs[0]); sB[1] = sptr(Bs[1]); sB[2] = sptr(Bs[2]);

    const int tid = threadIdx.x;
    const int lane = tid % 32;
    const int warp = tid / 32;
    const int gid = lane / 4;
    const int tig = lane % 4;
    const int wm = warp / 4;
    const int wn = warp % 4;
    const int m0 = blockIdx.y * 128;
    const int n0 = blockIdx.x * 128;

    const int arow = wm * 64 + (lane % 16);
    const int ga_add = lane / 16;
    const int brow = wn * 32 + ((lane / 16) % 2) * 8 + (lane % 8);
    const int gb_add = (lane / 8) % 2;

    float acc[4][4][4];
    for (int i = 0; i < 4; i++) {
        for (int j = 0; j < 4; j++) {
            for (int q = 0; q < 4; q++) { acc[i][j][q] = 0.f; }
        }
    }

    gemm_stage(sA[0], sB[0], Ap, Bp, m0, n0, 0, tid);
    cpcommit();
    gemm_stage(sA[1], sB[1], Ap, Bp, m0, n0, 32, tid);
    cpcommit();
    gemm_stage(sA[2], sB[2], Ap, Bp, m0, n0, 64, tid);
    cpcommit();

    for (int kk = 0; kk < 16; kk++) {
        if (kk < 14) { cpwait2(); }
        else if (kk == 14) { cpwait1(); }
        else { cpwait0(); }
        __syncthreads();
        int buf = kk % 3;
        const unsigned cA = sA[buf];
        const unsigned cB = sB[buf];

        for (int ks = 0; ks < 4; ks++) {
            unsigned af[4][4];
            unsigned bf[2][4];
            for (int mt = 0; mt < 4; mt++) {
                int r = arow + mt * 16;
                int grp = (ks * 2 + ga_add) ^ (r % 8);
                ldsm4(af[mt][0], af[mt][1], af[mt][2], af[mt][3], cA + r * 128 + grp * 16);
            }
            for (int p = 0; p < 2; p++) {
                int r = brow + p * 16;
                int grp = (ks * 2 + gb_add) ^ (r % 8);
                ldsm4(bf[p][0], bf[p][1], bf[p][2], bf[p][3], cB + r * 128 + grp * 16);
            }
            for (int mt = 0; mt < 4; mt++) {
                for (int p = 0; p < 2; p++) {
                    mma16(acc[mt][2 * p + 0], af[mt][0], af[mt][1], af[mt][2], af[mt][3],
                          bf[p][0], bf[p][1]);
                    mma16(acc[mt][2 * p + 1], af[mt][0], af[mt][1], af[mt][2], af[mt][3],
                          bf[p][2], bf[p][3]);
                }
            }
        }
        __syncthreads();
        if (kk < 13) {
            gemm_stage(sA[buf], sB[buf], Ap, Bp, m0, n0, (kk + 3) * 32, tid);
            cpcommit();
        }
    }

    for (int mt = 0; mt < 4; mt++) {
        for (int nt = 0; nt < 4; nt++) {
            int row = m0 + wm * 64 + mt * 16 + gid;
            int colu = (n0 + wn * 32 + nt * 8 + 2 * tig) / 2;
            Cp[row * Nu + colu] = pack_h2(acc[mt][nt][0], acc[mt][nt][1]);
            Cp[(row + 8) * Nu + colu] = pack_h2(acc[mt][nt][2], acc[mt][nt][3]);
        }
    }
}

// ---------------------------------------------------------------------------
// GEMM fp32 out + bias (output projection). 3-stage cp.async, 256 threads.
// ---------------------------------------------------------------------------
__global__ __launch_bounds__(256) void gemm_hh_f(
    const unsigned* __restrict__ Ap, const unsigned* __restrict__ Bp,
    float* __restrict__ Cp, const float* __restrict__ bias)
{
    __shared__ unsigned As[3][128 * 32];
    __shared__ unsigned Bs[3][128 * 32];
    unsigned sA[3];
    unsigned sB[3];
    sA[0] = sptr(As[0]); sA[1] = sptr(As[1]); sA[2] = sptr(As[2]);
    sB[0] = sptr(Bs[0]); sB[1] = sptr(Bs[1]); sB[2] = sptr(Bs[2]);

    const int tid = threadIdx.x;
    const int lane = tid % 32;
    const int warp = tid / 32;
    const int gid = lane / 4;
    const int tig = lane % 4;
    const int wm = warp / 4;
    const int wn = warp % 4;
    const int m0 = blockIdx.y * 128;
    const int n0 = blockIdx.x * 128;

    const int arow = wm * 64 + (lane % 16);
    const int ga_add = lane / 16;
    const int brow = wn * 32 + ((lane / 16) % 2) * 8 + (lane % 8);
    const int gb_add = (lane / 8) % 2;

    float acc[4][4][4];
    for (int i = 0; i < 4; i++) {
        for (int j = 0; j < 4; j++) {
            for (int q = 0; q < 4; q++) { acc[i][j][q] = 0.f; }
        }
    }

    gemm_stage(sA[0], sB[0], Ap, Bp, m0, n0, 0, tid);
    cpcommit();
    gemm_stage(sA[1], sB[1], Ap, Bp, m0, n0, 32, tid);
    cpcommit();
    gemm_stage(sA[2], sB[2], Ap, Bp, m0, n0, 64, tid);
    cpcommit();

    for (int kk = 0; kk < 16; kk++) {
        if (kk < 14) { cpwait2(); }
        else if (kk == 14) { cpwait1(); }
        else { cpwait0(); }
        __syncthreads();
        int buf = kk % 3;
        const unsigned cA = sA[buf];
        const unsigned cB = sB[buf];

        for (int ks = 0; ks < 4; ks++) {
            unsigned af[4][4];
            unsigned bf[2][4];
            for (int mt = 0; mt < 4; mt++) {
                int r = arow + mt * 16;
                int grp = (ks * 2 + ga_add) ^ (r % 8);
                ldsm4(af[mt][0], af[mt][1], af[mt][2], af[mt][3], cA + r * 128 + grp * 16);
            }
            for (int p = 0; p < 2; p++) {
                int r = brow + p * 16;
                int grp = (ks * 2 + gb_add) ^ (r % 8);
                ldsm4(bf[p][0], bf[p][1], bf[p][2], bf[p][3], cB + r * 128 + grp * 16);
            }
            for (int mt = 0; mt < 4; mt++) {
                for (int p = 0; p < 2; p++) {
                    mma16(acc[mt][2 * p + 0], af[mt][0], af[mt][1], af[mt][2], af[mt][3],
                          bf[p][0], bf[p][1]);
                    mma16(acc[mt][2 * p + 1], af[mt][0], af[mt][1], af[mt][2], af[mt][3],
                          bf[p][2], bf[p][3]);
                }
            }
        }
        __syncthreads();
        if (kk < 13) {
            gemm_stage(sA[buf], sB[buf], Ap, Bp, m0, n0, (kk + 3) * 32, tid);
            cpcommit();
        }
    }

    for (int mt = 0; mt < 4; mt++) {
        for (int nt = 0; nt < 4; nt++) {
            int row = m0 + wm * 64 + mt * 16 + gid;
            int col = n0 + wn * 32 + nt * 8 + 2 * tig;
            float bb0 = bias[col];
            float bb1 = bias[col + 1];
            *(float2*)(Cp + row * 1024 + col) =
                make_float2(acc[mt][nt][0] + bb0, acc[mt][nt][1] + bb1);
            *(float2*)(Cp + (row + 8) * 1024 + col) =
                make_float2(acc[mt][nt][2] + bb0, acc[mt][nt][3] + bb1);
        }
    }
}

// ---------------------------------------------------------------------------
// Flash attention: Br=128, 4 warps, 2-stage cp.async K/V pipeline (round-8).
// ---------------------------------------------------------------------------
__device__ __forceinline__ void kv_stage(
    unsigned sKb, unsigned sVb, const unsigned* __restrict__ kvrow0, int kt, int tid)
{
    int r = tid / 2;
    int rx = r % 8;
    const unsigned* src = kvrow0 + (kt * 64 + r) * 256;
    for (int j = 0; j < 4; j++) {
        int grp = j * 2 + (tid % 2);
        unsigned sw = (unsigned)((grp ^ rx) * 16);
        cpa16(sKb + r * 128 + sw, src + grp * 4);
        cpa16(sVb + r * 128 + sw, src + 128 + grp * 4);
    }
}

__global__ __launch_bounds__(128) void attn_h(
    const unsigned* __restrict__ qbuf, const unsigned* __restrict__ kvbuf,
    unsigned* __restrict__ obuf)
{
    __shared__ unsigned Qs[128 * 32];
    __shared__ unsigned Ks[2][64 * 32];
    __shared__ unsigned Vs[2][64 * 32];
    const unsigned sQ = sptr(Qs);
    unsigned sK[2];
    unsigned sV[2];
    sK[0] = sptr(Ks[0]); sK[1] = sptr(Ks[1]);
    sV[0] = sptr(Vs[0]); sV[1] = sptr(Vs[1]);

    const int tid = threadIdx.x;
    const int lane = tid % 32;
    const int warp = tid / 32;
    const int gid = lane / 4;
    const int tig = lane % 4;
    const int q0 = blockIdx.x * 128;
    const int bh = blockIdx.y;
    const int bb = bh / 16;
    const int hh = bh % 16;
    const int gg = hh / 4;

    const int kmax = q0 / 64 + 1;
    const unsigned* kvrow0 = kvbuf + (size_t)bb * TT * 256 + gg * 32;

    kv_stage(sK[0], sV[0], kvrow0, 0, tid);
    cpcommit();
    kv_stage(sK[1], sV[1], kvrow0, 1, tid);
    cpcommit();

    {
        const unsigned* srow = qbuf + (bb * TT + q0 + tid) * 512 + hh * 32;
        unsigned* drow = Qs + tid * 32;
        int rx = tid % 8;
        for (int grp = 0; grp < 8; grp++) {
            *(uint4*)(drow + (grp ^ rx) * 4) = *(const uint4*)(srow + grp * 4);
        }
    }
    __syncthreads();

    unsigned qf[2][4][4];
    const int qga = lane / 16;
    for (int mt = 0; mt < 2; mt++) {
        int qrow = warp * 32 + mt * 16 + (lane % 16);
        for (int ks = 0; ks < 4; ks++) {
            int grp = (ks * 2 + qga) ^ (qrow % 8);
            ldsm4(qf[mt][ks][0], qf[mt][ks][1], qf[mt][ks][2], qf[mt][ks][3],
                  sQ + qrow * 128 + grp * 16);
        }
    }

    float oacc[2][8][4];
    for (int mt = 0; mt < 2; mt++) {
        for (int nt = 0; nt < 8; nt++) {
            for (int q = 0; q < 4; q++) { oacc[mt][nt][q] = 0.f; }
        }
    }
    float mr[2][2];
    float lr[2][2];
    for (int mt = 0; mt < 2; mt++) {
        mr[mt][0] = -1e30f; mr[mt][1] = -1e30f;
        lr[mt][0] = 0.f; lr[mt][1] = 0.f;
    }

    const int rw0 = q0 + warp * 32;

    const int s_nadd = ((lane / 16) % 2) * 8 + (lane % 8);
    const int s_gadd = (lane / 8) % 2;
    const int v_kadd = ((lane / 8) % 2) * 8 + (lane % 8);
    const int v_gadd = (lane / 16) % 2;

    for (int kt = 0; kt <= kmax; kt++) {
        if (kt < kmax) { cpwait1(); } else { cpwait0(); }
        __syncthreads();
        const unsigned cK = sK[kt % 2];
        const unsigned cV = sV[kt % 2];

        if (kt * 64 <= rw0 + 31) {
            float sc[2][8][4];
            for (int mt = 0; mt < 2; mt++) {
                for (int nt = 0; nt < 8; nt++) {
                    for (int q = 0; q < 4; q++) { sc[mt][nt][q] = 0.f; }
                }
            }
            for (int ks = 0; ks < 4; ks++) {
                for (int p = 0; p < 4; p++) {
                    int nrow = p * 16 + s_nadd;
                    int grp = (ks * 2 + s_gadd) ^ (nrow % 8);
                    unsigned kf0, kf1, kf2, kf3;
                    ldsm4(kf0, kf1, kf2, kf3, cK + nrow * 128 + grp * 16);
                    for (int mt = 0; mt < 2; mt++) {
                        mma16(sc[mt][2 * p + 0], qf[mt][ks][0], qf[mt][ks][1], qf[mt][ks][2], qf[mt][ks][3], kf0, kf1);
                        mma16(sc[mt][2 * p + 1], qf[mt][ks][0], qf[mt][ks][1], qf[mt][ks][2], qf[mt][ks][3], kf2, kf3);
                    }
                }
            }

            if (kt * 64 + 63 > rw0) {
                for (int mt = 0; mt < 2; mt++) {
                    int rowA = rw0 + mt * 16 + gid;
                    int rowB = rowA + 8;
                    for (int nt = 0; nt < 8; nt++) {
                        int kcol = kt * 64 + nt * 8 + 2 * tig;
                        if (kcol > rowA) { sc[mt][nt][0] = -1e30f; }
                        if (kcol + 1 > rowA) { sc[mt][nt][1] = -1e30f; }
                        if (kcol > rowB) { sc[mt][nt][2] = -1e30f; }
                        if (kcol + 1 > rowB) { sc[mt][nt][3] = -1e30f; }
                    }
                }
            }

            for (int mt = 0; mt < 2; mt++) {
                float mt0 = -1e30f;
                float mt1 = -1e30f;
                for (int nt = 0; nt < 8; nt++) {
                    mt0 = fmaxf(mt0, fmaxf(sc[mt][nt][0], sc[mt][nt][1]));
                    mt1 = fmaxf(mt1, fmaxf(sc[mt][nt][2], sc[mt][nt][3]));
                }
                mt0 = fmaxf(mt0, __shfl_xor_sync(0xffffffffu, mt0, 1));
                mt0 = fmaxf(mt0, __shfl_xor_sync(0xffffffffu, mt0, 2));
                mt1 = fmaxf(mt1, __shfl_xor_sync(0xffffffffu, mt1, 1));
                mt1 = fmaxf(mt1, __shfl_xor_sync(0xffffffffu, mt1, 2));
                float mn0 = fmaxf(mr[mt][0], mt0);
                float mn1 = fmaxf(mr[mt][1], mt1);
                float c0 = __expf(mr[mt][0] - mn0);
                float c1 = __expf(mr[mt][1] - mn1);
                float ps0 = 0.f;
                float ps1 = 0.f;
                for (int nt = 0; nt < 8; nt++) {
                    sc[mt][nt][0] = __expf(sc[mt][nt][0] - mn0);
                    sc[mt][nt][1] = __expf(sc[mt][nt][1] - mn0);
                    sc[mt][nt][2] = __expf(sc[mt][nt][2] - mn1);
                    sc[mt][nt][3] = __expf(sc[mt][nt][3] - mn1);
                    ps0 += sc[mt][nt][0] + sc[mt][nt][1];
                    ps1 += sc[mt][nt][2] + sc[mt][nt][3];
                    oacc[mt][nt][0] *= c0;
                    oacc[mt][nt][1] *= c0;
                    oacc[mt][nt][2] *= c1;
                    oacc[mt][nt][3] *= c1;
                }
                ps0 += __shfl_xor_sync(0xffffffffu, ps0, 1);
                ps0 += __shfl_xor_sync(0xffffffffu, ps0, 2);
                ps1 += __shfl_xor_sync(0xffffffffu, ps1, 1);
                ps1 += __shfl_xor_sync(0xffffffffu, ps1, 2);
                lr[mt][0] = lr[mt][0] * c0 + ps0;
                lr[mt][1] = lr[mt][1] * c1 + ps1;
                mr[mt][0] = mn0;
                mr[mt][1] = mn1;
            }

            for (int ks = 0; ks < 4; ks++) {
                unsigned pf[2][4];
                for (int mt = 0; mt < 2; mt++) {
                    pf[mt][0] = pack_h2(sc[mt][2 * ks + 0][0], sc[mt][2 * ks + 0][1]);
                    pf[mt][1] = pack_h2(sc[mt][2 * ks + 0][2], sc[mt][2 * ks + 0][3]);
                    pf[mt][2] = pack_h2(sc[mt][2 * ks + 1][0], sc[mt][2 * ks + 1][1]);
                    pf[mt][3] = pack_h2(sc[mt][2 * ks + 1][2], sc[mt][2 * ks + 1][3]);
                }
                for (int p = 0; p < 4; p++) {
                    int krow = ks * 16 + v_kadd;
                    int grp = (p * 2 + v_gadd) ^ (krow % 8);
                    unsigned vf0, vf1, vf2, vf3;
                    ldsm4t(vf0, vf1, vf2, vf3, cV + krow * 128 + grp * 16);
                    for (int mt = 0; mt < 2; mt++) {
                        mma16(oacc[mt][2 * p + 0], pf[mt][0], pf[mt][1], pf[mt][2], pf[mt][3], vf0, vf1);
                        mma16(oacc[mt][2 * p + 1], pf[mt][0], pf[mt][1], pf[mt][2], pf[mt][3], vf2, vf3);
                    }
                }
            }
        }

        __syncthreads();
        if (kt + 2 <= kmax) {
            kv_stage(sK[kt % 2], sV[kt % 2], kvrow0, kt + 2, tid);
            cpcommit();
        }
    }

    for (int mt = 0; mt < 2; mt++) {
        float i0 = 1.f / lr[mt][0];
        float i1 = 1.f / lr[mt][1];
        int rowA = rw0 + mt * 16 + gid;
        int rowB = rowA + 8;
        for (int nt = 0; nt < 8; nt++) {
            int colu = hh * 32 + nt * 4 + tig;
            obuf[(bb * TT + rowA) * 512 + colu] = pack_h2(oacc[mt][nt][0] * i0, oacc[mt][nt][1] * i0);
            obuf[(bb * TT + rowB) * 512 + colu] = pack_h2(oacc[mt][nt][2] * i1, oacc[mt][nt][3] * i1);
        }
    }
}

extern "C" void kernel_launch(void* const* d_in, const int* in_sizes, int n_in,
                              void* d_out, int out_size)
{
    const float* x  = (const float*)d_in[0];
    const float* Wq = (const float*)d_in[1];
    const float* Wk = (const float*)d_in[2];
    const float* Wv = (const float*)d_in[3];
    const float* Wp = (const float*)d_in[4];
    const float* bp = (const float*)d_in[5];
    float* out = (float*)d_out;

    unsigned* gx = 0;
    unsigned* gwq = 0;
    unsigned* gwkv = 0;
    unsigned* gwp = 0;
    unsigned* gq = 0;
    unsigned* gkv = 0;
    unsigned* ga = 0;
    cudaGetSymbolAddress((void**)&gx, g_x);
    cudaGetSymbolAddress((void**)&gwq, g_wq);
    cudaGetSymbolAddress((void**)&gwkv, g_wkv);
    cudaGetSymbolAddress((void**)&gwp, g_wp);
    cudaGetSymbolAddress((void**)&gq, g_q);
    cudaGetSymbolAddress((void**)&gkv, g_kv);
    cudaGetSymbolAddress((void**)&ga, g_attn);

    conv_f2h<<<8192, 256>>>(x, gx, 2097152, 1.f);
    conv_f2h<<<1024, 256>>>(Wq, gwq, 262144, 0.125f);
    conv_f2h<<<256, 256>>>(Wk, gwkv, 65536, 1.f);
    conv_f2h<<<256, 256>>>(Wv, gwkv + 256 * 512, 65536, 1.f);
    conv_f2h<<<1024, 256>>>(Wp, gwp, 262144, 1.f);

    gemm_hh_h<<<dim3(8, 64), 256>>>(gx, gwq, gq, 512);
    gemm_hh_h<<<dim3(4, 64), 256>>>(gx, gwkv, gkv, 256);

    attn_h<<<dim3(16, 64), 128>>>(gq, gkv, ga);

    gemm_hh_f<<<dim3(8, 64), 256>>>(ga, gwp, out, bp);
}

// round 12
// speedup vs baseline: 1.2853x; 1.0078x over previous
#include <cuda_runtime.h>

#define TT 2048
#define BATCH 4

// fp16 packed-pair scratch (1 unsigned = 2 halves). Allocation is forbidden.
__device__ unsigned g_x[(size_t)BATCH * TT * 512];      // x fp16 [b,t,1024h]
__device__ unsigned g_wqkv[512 * 1536];                 // [Wq*0.125 (1024r) | Wk (256r) | Wv (256r)]
__device__ unsigned g_wp[512 * 1024];
__device__ unsigned g_qkv[(size_t)BATCH * TT * 768];    // [b,t, q 512u | k 128u | v 128u]
__device__ unsigned g_attn[(size_t)BATCH * TT * 512];

__device__ __forceinline__ unsigned sptr(const void* p) {
    return (unsigned)__cvta_generic_to_shared(p);
}

__device__ __forceinline__ unsigned pack_h2(float lo, float hi) {
    unsigned r;
    asm("cvt.rn.f16x2.f32 %0, %1, %2;" : "=r"(r) : "f"(hi), "f"(lo));
    return r;
}

__device__ __forceinline__ void cpa16(unsigned daddr, const void* src) {
    asm volatile("cp.async.cg.shared.global [%0], [%1], 16;" :: "r"(daddr), "l"(src));
}
__device__ __forceinline__ void cpcommit() {
    asm volatile("cp.async.commit_group;");
}
__device__ __forceinline__ void cpwait0() {
    asm volatile("cp.async.wait_group 0;");
}
__device__ __forceinline__ void cpwait1() {
    asm volatile("cp.async.wait_group 1;");
}
__device__ __forceinline__ void cpwait2() {
    asm volatile("cp.async.wait_group 2;");
}

__device__ __forceinline__ void ldsm4(unsigned& r0, unsigned& r1, unsigned& r2, unsigned& r3, unsigned a) {
    asm volatile("ldmatrix.sync.aligned.m8n8.x4.shared.b16 {%0,%1,%2,%3},[%4];"
                 : "=r"(r0), "=r"(r1), "=r"(r2), "=r"(r3) : "r"(a));
}

__device__ __forceinline__ void ldsm4t(unsigned& r0, unsigned& r1, unsigned& r2, unsigned& r3, unsigned a) {
    asm volatile("ldmatrix.sync.aligned.m8n8.x4.trans.shared.b16 {%0,%1,%2,%3},[%4];"
                 : "=r"(r0), "=r"(r1), "=r"(r2), "=r"(r3) : "r"(a));
}

__device__ __forceinline__ void mma16(float* d,
                                      unsigned a0, unsigned a1, unsigned a2, unsigned a3,
                                      unsigned b0, unsigned b1) {
    asm volatile("mma.sync.aligned.m16n8k16.row.col.f32.f16.f16.f32 "
                 "{%0,%1,%2,%3},{%4,%5,%6,%7},{%8,%9},{%0,%1,%2,%3};"
                 : "+f"(d[0]), "+f"(d[1]), "+f"(d[2]), "+f"(d[3])
                 : "r"(a0), "r"(a1), "r"(a2), "r"(a3), "r"(b0), "r"(b1));
}

// ---------------------------------------------------------------------------
// Single conversion kernel: all fp32 inputs -> fp16 scratch, segmented.
// Segments (in float4 units): x 2097152 | Wq 262144 | Wk 65536 | Wv 65536 | Wp 262144.
// ---------------------------------------------------------------------------
__global__ __launch_bounds__(256) void conv_all(
    const float* __restrict__ x, const float* __restrict__ Wq,
    const float* __restrict__ Wk, const float* __restrict__ Wv,
    const float* __restrict__ Wp,
    unsigned* __restrict__ gx, unsigned* __restrict__ gwqkv,
    unsigned* __restrict__ gwp)
{
    int i = blockIdx.x * 256 + threadIdx.x;
    const float* src;
    uint2* dst;
    int idx;
    float scale = 1.f;
    if (i < 2097152) {
        src = x; dst = (uint2*)gx; idx = i;
    } else if (i < 2359296) {
        src = Wq; dst = (uint2*)gwqkv; idx = i - 2097152; scale = 0.125f;
    } else if (i < 2424832) {
        src = Wk; dst = (uint2*)gwqkv + 262144; idx = i - 2359296;
    } else if (i < 2490368) {
        src = Wv; dst = (uint2*)gwqkv + 327680; idx = i - 2424832;
    } else if (i < 2752512) {
        src = Wp; dst = (uint2*)gwp; idx = i - 2490368;
    } else {
        return;
    }
    float4 f = ((const float4*)src)[idx];
    uint2 u;
    u.x = pack_h2(f.x * scale, f.y * scale);
    u.y = pack_h2(f.z * scale, f.w * scale);
    dst[idx] = u;
}

// ---------------------------------------------------------------------------
// Stage one BK=64 slab of A and B into swizzled shared (cp.async, 8x16B/thread,
// 256 threads).
// ---------------------------------------------------------------------------
__device__ __forceinline__ void gemm_stage(
    unsigned sAb, unsigned sBb,
    const unsigned* __restrict__ Ap, const unsigned* __restrict__ Bp,
    int m0, int n0, int k0u, int tid)
{
    int tr = tid / 4;
    int tg = (tid % 4) * 2;
    for (int i = 0; i < 2; i++) {
        int row = tr + i * 64;
        int rx = row % 8;
        for (int j = 0; j < 2; j++) {
            int grp = tg + j;
            cpa16(sAb + (row * 32 + (grp ^ rx) * 4) * 4, Ap + (m0 + row) * 512 + k0u + grp * 4);
            cpa16(sBb + (row * 32 + (grp ^ rx) * 4) * 4, Bp + (n0 + row) * 512 + k0u + grp * 4);
        }
    }
}

// ---------------------------------------------------------------------------
// GEMM fp16 out: C[M, 2*Nu h] = A[M,1024] @ B[N,1024]^T. 3-stage cp.async,
// 256 threads, 8 warps (warp tile 64x32).
// ---------------------------------------------------------------------------
__global__ __launch_bounds__(256) void gemm_hh_h(
    const unsigned* __restrict__ Ap, const unsigned* __restrict__ Bp,
    unsigned* __restrict__ Cp, int Nu)
{
    __shared__ unsigned As[3][128 * 32];
    __shared__ unsigned Bs[3][128 * 32];
    unsigned sA[3];
    unsigned sB[3];
    sA[0] = sptr(As[0]); sA[1] = sptr(As[1]); sA[2] = sptr(As[2]);
    sB[0] = sptr(Bs[0]); sB[1] = sptr(Bs[1]); sB[2] = sptr(Bs[2]);

    const int tid = threadIdx.x;
    const int lane = tid % 32;
    const int warp = tid / 32;
    const int gid = lane / 4;
    const int tig = lane % 4;
    const int wm = warp / 4;
    const int wn = warp % 4;
    const int m0 = blockIdx.y * 128;
    const int n0 = blockIdx.x * 128;

    const int arow = wm * 64 + (lane % 16);
    const int ga_add = lane / 16;
    const int brow = wn * 32 + ((lane / 16) % 2) * 8 + (lane % 8);
    const int gb_add = (lane / 8) % 2;

    float acc[4][4][4];
    for (int i = 0; i < 4; i++) {
        for (int j = 0; j < 4; j++) {
            for (int q = 0; q < 4; q++) { acc[i][j][q] = 0.f; }
        }
    }

    gemm_stage(sA[0], sB[0], Ap, Bp, m0, n0, 0, tid);
    cpcommit();
    gemm_stage(sA[1], sB[1], Ap, Bp, m0, n0, 32, tid);
    cpcommit();
    gemm_stage(sA[2], sB[2], Ap, Bp, m0, n0, 64, tid);
    cpcommit();

    for (int kk = 0; kk < 16; kk++) {
        if (kk < 14) { cpwait2(); }
        else if (kk == 14) { cpwait1(); }
        else { cpwait0(); }
        __syncthreads();
        int buf = kk % 3;
        const unsigned cA = sA[buf];
        const unsigned cB = sB[buf];

        for (int ks = 0; ks < 4; ks++) {
            unsigned af[4][4];
            unsigned bf[2][4];
            for (int mt = 0; mt < 4; mt++) {
                int r = arow + mt * 16;
                int grp = (ks * 2 + ga_add) ^ (r % 8);
                ldsm4(af[mt][0], af[mt][1], af[mt][2], af[mt][3], cA + r * 128 + grp * 16);
            }
            for (int p = 0; p < 2; p++) {
                int r = brow + p * 16;
                int grp = (ks * 2 + gb_add) ^ (r % 8);
                ldsm4(bf[p][0], bf[p][1], bf[p][2], bf[p][3], cB + r * 128 + grp * 16);
            }
            for (int mt = 0; mt < 4; mt++) {
                for (int p = 0; p < 2; p++) {
                    mma16(acc[mt][2 * p + 0], af[mt][0], af[mt][1], af[mt][2], af[mt][3],
                          bf[p][0], bf[p][1]);
                    mma16(acc[mt][2 * p + 1], af[mt][0], af[mt][1], af[mt][2], af[mt][3],
                          bf[p][2], bf[p][3]);
                }
            }
        }
        __syncthreads();
        if (kk < 13) {
            gemm_stage(sA[buf], sB[buf], Ap, Bp, m0, n0, (kk + 3) * 32, tid);
            cpcommit();
        }
    }

    for (int mt = 0; mt < 4; mt++) {
        for (int nt = 0; nt < 4; nt++) {
            int row = m0 + wm * 64 + mt * 16 + gid;
            int colu = (n0 + wn * 32 + nt * 8 + 2 * tig) / 2;
            Cp[row * Nu + colu] = pack_h2(acc[mt][nt][0], acc[mt][nt][1]);
            Cp[(row + 8) * Nu + colu] = pack_h2(acc[mt][nt][2], acc[mt][nt][3]);
        }
    }
}

// ---------------------------------------------------------------------------
// GEMM fp32 out + bias (output projection). 3-stage cp.async, 256 threads.
// ---------------------------------------------------------------------------
__global__ __launch_bounds__(256) void gemm_hh_f(
    const unsigned* __restrict__ Ap, const unsigned* __restrict__ Bp,
    float* __restrict__ Cp, const float* __restrict__ bias)
{
    __shared__ unsigned As[3][128 * 32];
    __shared__ unsigned Bs[3][128 * 32];
    unsigned sA[3];
    unsigned sB[3];
    sA[0] = sptr(As[0]); sA[1] = sptr(As[1]); sA[2] = sptr(As[2]);
    sB[0] = sptr(Bs[0]); sB[1] = sptr(Bs[1]); sB[2] = sptr(Bs[2]);

    const int tid = threadIdx.x;
    const int lane = tid % 32;
    const int warp = tid / 32;
    const int gid = lane / 4;
    const int tig = lane % 4;
    const int wm = warp / 4;
    const int wn = warp % 4;
    const int m0 = blockIdx.y * 128;
    const int n0 = blockIdx.x * 128;

    const int arow = wm * 64 + (lane % 16);
    const int ga_add = lane / 16;
    const int brow = wn * 32 + ((lane / 16) % 2) * 8 + (lane % 8);
    const int gb_add = (lane / 8) % 2;

    float acc[4][4][4];
    for (int i = 0; i < 4; i++) {
        for (int j = 0; j < 4; j++) {
            for (int q = 0; q < 4; q++) { acc[i][j][q] = 0.f; }
        }
    }

    gemm_stage(sA[0], sB[0], Ap, Bp, m0, n0, 0, tid);
    cpcommit();
    gemm_stage(sA[1], sB[1], Ap, Bp, m0, n0, 32, tid);
    cpcommit();
    gemm_stage(sA[2], sB[2], Ap, Bp, m0, n0, 64, tid);
    cpcommit();

    for (int kk = 0; kk < 16; kk++) {
        if (kk < 14) { cpwait2(); }
        else if (kk == 14) { cpwait1(); }
        else { cpwait0(); }
        __syncthreads();
        int buf = kk % 3;
        const unsigned cA = sA[buf];
        const unsigned cB = sB[buf];

        for (int ks = 0; ks < 4; ks++) {
            unsigned af[4][4];
            unsigned bf[2][4];
            for (int mt = 0; mt < 4; mt++) {
                int r = arow + mt * 16;
                int grp = (ks * 2 + ga_add) ^ (r % 8);
                ldsm4(af[mt][0], af[mt][1], af[mt][2], af[mt][3], cA + r * 128 + grp * 16);
            }
            for (int p = 0; p < 2; p++) {
                int r = brow + p * 16;
                int grp = (ks * 2 + gb_add) ^ (r % 8);
                ldsm4(bf[p][0], bf[p][1], bf[p][2], bf[p][3], cB + r * 128 + grp * 16);
            }
            for (int mt = 0; mt < 4; mt++) {
                for (int p = 0; p < 2; p++) {
                    mma16(acc[mt][2 * p + 0], af[mt][0], af[mt][1], af[mt][2], af[mt][3],
                          bf[p][0], bf[p][1]);
                    mma16(acc[mt][2 * p + 1], af[mt][0], af[mt][1], af[mt][2], af[mt][3],
                          bf[p][2], bf[p][3]);
                }
            }
        }
        __syncthreads();
        if (kk < 13) {
            gemm_stage(sA[buf], sB[buf], Ap, Bp, m0, n0, (kk + 3) * 32, tid);
            cpcommit();
        }
    }

    for (int mt = 0; mt < 4; mt++) {
        for (int nt = 0; nt < 4; nt++) {
            int row = m0 + wm * 64 + mt * 16 + gid;
            int col = n0 + wn * 32 + nt * 8 + 2 * tig;
            float bb0 = bias[col];
            float bb1 = bias[col + 1];
            *(float2*)(Cp + row * 1024 + col) =
                make_float2(acc[mt][nt][0] + bb0, acc[mt][nt][1] + bb1);
            *(float2*)(Cp + (row + 8) * 1024 + col) =
                make_float2(acc[mt][nt][2] + bb0, acc[mt][nt][3] + bb1);
        }
    }
}

// ---------------------------------------------------------------------------
// Flash attention: Br=128, 4 warps, 2-stage cp.async K/V pipeline.
// Reads from combined qkv buffer: row stride 768u, q at +0, k at +512, v at +640.
// ---------------------------------------------------------------------------
__device__ __forceinline__ void kv_stage(
    unsigned sKb, unsigned sVb, const unsigned* __restrict__ kvrow0, int kt, int tid)
{
    int r = tid / 2;
    int rx = r % 8;
    const unsigned* src = kvrow0 + (kt * 64 + r) * 768;
    for (int j = 0; j < 4; j++) {
        int grp = j * 2 + (tid % 2);
        unsigned sw = (unsigned)((grp ^ rx) * 16);
        cpa16(sKb + r * 128 + sw, src + grp * 4);
        cpa16(sVb + r * 128 + sw, src + 128 + grp * 4);
    }
}

__global__ __launch_bounds__(128) void attn_h(
    const unsigned* __restrict__ qkvbuf, unsigned* __restrict__ obuf)
{
    __shared__ unsigned Qs[128 * 32];
    __shared__ unsigned Ks[2][64 * 32];
    __shared__ unsigned Vs[2][64 * 32];
    const unsigned sQ = sptr(Qs);
    unsigned sK[2];
    unsigned sV[2];
    sK[0] = sptr(Ks[0]); sK[1] = sptr(Ks[1]);
    sV[0] = sptr(Vs[0]); sV[1] = sptr(Vs[1]);

    const int tid = threadIdx.x;
    const int lane = tid % 32;
    const int warp = tid / 32;
    const int gid = lane / 4;
    const int tig = lane % 4;
    const int q0 = blockIdx.x * 128;
    const int bh = blockIdx.y;
    const int bb = bh / 16;
    const int hh = bh % 16;
    const int gg = hh / 4;

    const int kmax = q0 / 64 + 1;
    const unsigned* kvrow0 = qkvbuf + (size_t)bb * TT * 768 + 512 + gg * 32;

    kv_stage(sK[0], sV[0], kvrow0, 0, tid);
    cpcommit();
    kv_stage(sK[1], sV[1], kvrow0, 1, tid);
    cpcommit();

    {
        const unsigned* srow = qkvbuf + ((size_t)bb * TT + q0 + tid) * 768 + hh * 32;
        unsigned* drow = Qs + tid * 32;
        int rx = tid % 8;
        for (int grp = 0; grp < 8; grp++) {
            *(uint4*)(drow + (grp ^ rx) * 4) = *(const uint4*)(srow + grp * 4);
        }
    }
    __syncthreads();

    unsigned qf[2][4][4];
    const int qga = lane / 16;
    for (int mt = 0; mt < 2; mt++) {
        int qrow = warp * 32 + mt * 16 + (lane % 16);
        for (int ks = 0; ks < 4; ks++) {
            int grp = (ks * 2 + qga) ^ (qrow % 8);
            ldsm4(qf[mt][ks][0], qf[mt][ks][1], qf[mt][ks][2], qf[mt][ks][3],
                  sQ + qrow * 128 + grp * 16);
        }
    }

    float oacc[2][8][4];
    for (int mt = 0; mt < 2; mt++) {
        for (int nt = 0; nt < 8; nt++) {
            for (int q = 0; q < 4; q++) { oacc[mt][nt][q] = 0.f; }
        }
    }
    float mr[2][2];
    float lr[2][2];
    for (int mt = 0; mt < 2; mt++) {
        mr[mt][0] = -1e30f; mr[mt][1] = -1e30f;
        lr[mt][0] = 0.f; lr[mt][1] = 0.f;
    }

    const int rw0 = q0 + warp * 32;

    const int s_nadd = ((lane / 16) % 2) * 8 + (lane % 8);
    const int s_gadd = (lane / 8) % 2;
    const int v_kadd = ((lane / 8) % 2) * 8 + (lane % 8);
    const int v_gadd = (lane / 16) % 2;

    for (int kt = 0; kt <= kmax; kt++) {
        if (kt < kmax) { cpwait1(); } else { cpwait0(); }
        __syncthreads();
        const unsigned cK = sK[kt % 2];
        const unsigned cV = sV[kt % 2];

        if (kt * 64 <= rw0 + 31) {
            float sc[2][8][4];
            for (int mt = 0; mt < 2; mt++) {
                for (int nt = 0; nt < 8; nt++) {
                    for (int q = 0; q < 4; q++) { sc[mt][nt][q] = 0.f; }
                }
            }
            for (int ks = 0; ks < 4; ks++) {
                for (int p = 0; p < 4; p++) {
                    int nrow = p * 16 + s_nadd;
                    int grp = (ks * 2 + s_gadd) ^ (nrow % 8);
                    unsigned kf0, kf1, kf2, kf3;
                    ldsm4(kf0, kf1, kf2, kf3, cK + nrow * 128 + grp * 16);
                    for (int mt = 0; mt < 2; mt++) {
                        mma16(sc[mt][2 * p + 0], qf[mt][ks][0], qf[mt][ks][1], qf[mt][ks][2], qf[mt][ks][3], kf0, kf1);
                        mma16(sc[mt][2 * p + 1], qf[mt][ks][0], qf[mt][ks][1], qf[mt][ks][2], qf[mt][ks][3], kf2, kf3);
                    }
                }
            }

            if (kt * 64 + 63 > rw0) {
                for (int mt = 0; mt < 2; mt++) {
                    int rowA = rw0 + mt * 16 + gid;
                    int rowB = rowA + 8;
                    for (int nt = 0; nt < 8; nt++) {
                        int kcol = kt * 64 + nt * 8 + 2 * tig;
                        if (kcol > rowA) { sc[mt][nt][0] = -1e30f; }
                        if (kcol + 1 > rowA) { sc[mt][nt][1] = -1e30f; }
                        if (kcol > rowB) { sc[mt][nt][2] = -1e30f; }
                        if (kcol + 1 > rowB) { sc[mt][nt][3] = -1e30f; }
                    }
                }
            }

            for (int mt = 0; mt < 2; mt++) {
                float mt0 = -1e30f;
                float mt1 = -1e30f;
                for (int nt = 0; nt < 8; nt++) {
                    mt0 = fmaxf(mt0, fmaxf(sc[mt][nt][0], sc[mt][nt][1]));
                    mt1 = fmaxf(mt1, fmaxf(sc[mt][nt][2], sc[mt][nt][3]));
                }
                mt0 = fmaxf(mt0, __shfl_xor_sync(0xffffffffu, mt0, 1));
                mt0 = fmaxf(mt0, __shfl_xor_sync(0xffffffffu, mt0, 2));
                mt1 = fmaxf(mt1, __shfl_xor_sync(0xffffffffu, mt1, 1));
                mt1 = fmaxf(mt1, __shfl_xor_sync(0xffffffffu, mt1, 2));
                float mn0 = fmaxf(mr[mt][0], mt0);
                float mn1 = fmaxf(mr[mt][1], mt1);
                float c0 = __expf(mr[mt][0] - mn0);
                float c1 = __expf(mr[mt][1] - mn1);
                float ps0 = 0.f;
                float ps1 = 0.f;
                for (int nt = 0; nt < 8; nt++) {
                    sc[mt][nt][0] = __expf(sc[mt][nt][0] - mn0);
                    sc[mt][nt][1] = __expf(sc[mt][nt][1] - mn0);
                    sc[mt][nt][2] = __expf(sc[mt][nt][2] - mn1);
                    sc[mt][nt][3] = __expf(sc[mt][nt][3] - mn1);
                    ps0 += sc[mt][nt][0] + sc[mt][nt][1];
                    ps1 += sc[mt][nt][2] + sc[mt][nt][3];
                    oacc[mt][nt][0] *= c0;
                    oacc[mt][nt][1] *= c0;
                    oacc[mt][nt][2] *= c1;
                    oacc[mt][nt][3] *= c1;
                }
                ps0 += __shfl_xor_sync(0xffffffffu, ps0, 1);
                ps0 += __shfl_xor_sync(0xffffffffu, ps0, 2);
                ps1 += __shfl_xor_sync(0xffffffffu, ps1, 1);
                ps1 += __shfl_xor_sync(0xffffffffu, ps1, 2);
                lr[mt][0] = lr[mt][0] * c0 + ps0;
                lr[mt][1] = lr[mt][1] * c1 + ps1;
                mr[mt][0] = mn0;
                mr[mt][1] = mn1;
            }

            for (int ks = 0; ks < 4; ks++) {
                unsigned pf[2][4];
                for (int mt = 0; mt < 2; mt++) {
                    pf[mt][0] = pack_h2(sc[mt][2 * ks + 0][0], sc[mt][2 * ks + 0][1]);
                    pf[mt][1] = pack_h2(sc[mt][2 * ks + 0][2], sc[mt][2 * ks + 0][3]);
                    pf[mt][2] = pack_h2(sc[mt][2 * ks + 1][0], sc[mt][2 * ks + 1][1]);
                    pf[mt][3] = pack_h2(sc[mt][2 * ks + 1][2], sc[mt][2 * ks + 1][3]);
                }
                for (int p = 0; p < 4; p++) {
                    int krow = ks * 16 + v_kadd;
                    int grp = (p * 2 + v_gadd) ^ (krow % 8);
                    unsigned vf0, vf1, vf2, vf3;
                    ldsm4t(vf0, vf1, vf2, vf3, cV + krow * 128 + grp * 16);
                    for (int mt = 0; mt < 2; mt++) {
                        mma16(oacc[mt][2 * p + 0], pf[mt][0], pf[mt][1], pf[mt][2], pf[mt][3], vf0, vf1);
                        mma16(oacc[mt][2 * p + 1], pf[mt][0], pf[mt][1], pf[mt][2], pf[mt][3], vf2, vf3);
                    }
                }
            }
        }

        __syncthreads();
        if (kt + 2 <= kmax) {
            kv_stage(sK[kt % 2], sV[kt % 2], kvrow0, kt + 2, tid);
            cpcommit();
        }
    }

    for (int mt = 0; mt < 2; mt++) {
        float i0 = 1.f / lr[mt][0];
        float i1 = 1.f / lr[mt][1];
        int rowA = rw0 + mt * 16 + gid;
        int rowB = rowA + 8;
        for (int nt = 0; nt < 8; nt++) {
            int colu = hh * 32 + nt * 4 + tig;
            obuf[((size_t)bb * TT + rowA) * 512 + colu] = pack_h2(oacc[mt][nt][0] * i0, oacc[mt][nt][1] * i0);
            obuf[((size_t)bb * TT + rowB) * 512 + colu] = pack_h2(oacc[mt][nt][2] * i1, oacc[mt][nt][3] * i1);
        }
    }
}

extern "C" void kernel_launch(void* const* d_in, const int* in_sizes, int n_in,
                              void* d_out, int out_size)
{
    const float* x  = (const float*)d_in[0];
    const float* Wq = (const float*)d_in[1];
    const float* Wk = (const float*)d_in[2];
    const float* Wv = (const float*)d_in[3];
    const float* Wp = (const float*)d_in[4];
    const float* bp = (const float*)d_in[5];
    float* out = (float*)d_out;

    unsigned* gx = 0;
    unsigned* gwqkv = 0;
    unsigned* gwp = 0;
    unsigned* gqkv = 0;
    unsigned* ga = 0;
    cudaGetSymbolAddress((void**)&gx, g_x);
    cudaGetSymbolAddress((void**)&gwqkv, g_wqkv);
    cudaGetSymbolAddress((void**)&gwp, g_wp);
    cudaGetSymbolAddress((void**)&gqkv, g_qkv);
    cudaGetSymbolAddress((void**)&ga, g_attn);

    conv_all<<<10752, 256>>>(x, Wq, Wk, Wv, Wp, gx, gwqkv, gwp);

    gemm_hh_h<<<dim3(12, 64), 256>>>(gx, gwqkv, gqkv, 768);

    attn_h<<<dim3(16, 64), 128>>>(gqkv, ga);

    gemm_hh_f<<<dim3(8, 64), 256>>>(ga, gwp, out, bp);
}

// round 13
// speedup vs baseline: 1.4441x; 1.1235x over previous
#include <cuda_runtime.h>

#define TT 2048
#define BATCH 4

// fp16 packed-pair scratch (1 unsigned = 2 halves). Allocation is forbidden.
__device__ unsigned g_x[(size_t)BATCH * TT * 512];      // x fp16 [b,t,1024h]
__device__ unsigned g_wqkv[512 * 1536];                 // [Wq*0.125 (1024r) | Wk (256r) | Wv (256r)]
__device__ unsigned g_wp[512 * 1024];
__device__ unsigned g_qkv[(size_t)BATCH * TT * 768];    // [b,t, q 512u | k 128u | v 128u]
__device__ unsigned g_attn[(size_t)BATCH * TT * 512];

__device__ __forceinline__ unsigned sptr(const void* p) {
    return (unsigned)__cvta_generic_to_shared(p);
}

__device__ __forceinline__ unsigned pack_h2(float lo, float hi) {
    unsigned r;
    asm("cvt.rn.f16x2.f32 %0, %1, %2;" : "=r"(r) : "f"(hi), "f"(lo));
    return r;
}

__device__ __forceinline__ void cpa16(unsigned daddr, const void* src) {
    asm volatile("cp.async.cg.shared.global [%0], [%1], 16;" :: "r"(daddr), "l"(src));
}
__device__ __forceinline__ void cpcommit() {
    asm volatile("cp.async.commit_group;");
}
__device__ __forceinline__ void cpwait0() {
    asm volatile("cp.async.wait_group 0;");
}
__device__ __forceinline__ void cpwait1() {
    asm volatile("cp.async.wait_group 1;");
}
__device__ __forceinline__ void cpwait2() {
    asm volatile("cp.async.wait_group 2;");
}

__device__ __forceinline__ void ldsm4(unsigned& r0, unsigned& r1, unsigned& r2, unsigned& r3, unsigned a) {
    asm volatile("ldmatrix.sync.aligned.m8n8.x4.shared.b16 {%0,%1,%2,%3},[%4];"
                 : "=r"(r0), "=r"(r1), "=r"(r2), "=r"(r3) : "r"(a));
}

__device__ __forceinline__ void ldsm4t(unsigned& r0, unsigned& r1, unsigned& r2, unsigned& r3, unsigned a) {
    asm volatile("ldmatrix.sync.aligned.m8n8.x4.trans.shared.b16 {%0,%1,%2,%3},[%4];"
                 : "=r"(r0), "=r"(r1), "=r"(r2), "=r"(r3) : "r"(a));
}

__device__ __forceinline__ void mma16(float* d,
                                      unsigned a0, unsigned a1, unsigned a2, unsigned a3,
                                      unsigned b0, unsigned b1) {
    asm volatile("mma.sync.aligned.m16n8k16.row.col.f32.f16.f16.f32 "
                 "{%0,%1,%2,%3},{%4,%5,%6,%7},{%8,%9},{%0,%1,%2,%3};"
                 : "+f"(d[0]), "+f"(d[1]), "+f"(d[2]), "+f"(d[3])
                 : "r"(a0), "r"(a1), "r"(a2), "r"(a3), "r"(b0), "r"(b1));
}

// ---------------------------------------------------------------------------
// Single conversion kernel: all fp32 inputs -> fp16 scratch, segmented.
// ---------------------------------------------------------------------------
__global__ __launch_bounds__(256) void conv_all(
    const float* __restrict__ x, const float* __restrict__ Wq,
    const float* __restrict__ Wk, const float* __restrict__ Wv,
    const float* __restrict__ Wp,
    unsigned* __restrict__ gx, unsigned* __restrict__ gwqkv,
    unsigned* __restrict__ gwp)
{
    int i = blockIdx.x * 256 + threadIdx.x;
    const float* src;
    uint2* dst;
    int idx;
    float scale = 1.f;
    if (i < 2097152) {
        src = x; dst = (uint2*)gx; idx = i;
    } else if (i < 2359296) {
        src = Wq; dst = (uint2*)gwqkv; idx = i - 2097152; scale = 0.125f;
    } else if (i < 2424832) {
        src = Wk; dst = (uint2*)gwqkv + 262144; idx = i - 2359296;
    } else if (i < 2490368) {
        src = Wv; dst = (uint2*)gwqkv + 327680; idx = i - 2424832;
    } else if (i < 2752512) {
        src = Wp; dst = (uint2*)gwp; idx = i - 2490368;
    } else {
        return;
    }
    float4 f = ((const float4*)src)[idx];
    uint2 u;
    u.x = pack_h2(f.x * scale, f.y * scale);
    u.y = pack_h2(f.z * scale, f.w * scale);
    dst[idx] = u;
}

// ---------------------------------------------------------------------------
// Stage one BK=64 slab of A and B into swizzled shared (cp.async, 8x16B/thread,
// 256 threads).
// ---------------------------------------------------------------------------
__device__ __forceinline__ void gemm_stage(
    unsigned sAb, unsigned sBb,
    const unsigned* __restrict__ Ap, const unsigned* __restrict__ Bp,
    int m0, int n0, int k0u, int tid)
{
    int tr = tid / 4;
    int tg = (tid % 4) * 2;
    for (int i = 0; i < 2; i++) {
        int row = tr + i * 64;
        int rx = row % 8;
        for (int j = 0; j < 2; j++) {
            int grp = tg + j;
            cpa16(sAb + (row * 32 + (grp ^ rx) * 4) * 4, Ap + (m0 + row) * 512 + k0u + grp * 4);
            cpa16(sBb + (row * 32 + (grp ^ rx) * 4) * 4, Bp + (n0 + row) * 512 + k0u + grp * 4);
        }
    }
}

// ---------------------------------------------------------------------------
// GEMM fp16 out: C[M, 2*Nu h] = A[M,1024] @ B[N,1024]^T. 3-stage cp.async,
// 256 threads, 8 warps (warp tile 64x32).
// ---------------------------------------------------------------------------
__global__ __launch_bounds__(256) void gemm_hh_h(
    const unsigned* __restrict__ Ap, const unsigned* __restrict__ Bp,
    unsigned* __restrict__ Cp, int Nu)
{
    __shared__ unsigned As[3][128 * 32];
    __shared__ unsigned Bs[3][128 * 32];
    unsigned sA[3];
    unsigned sB[3];
    sA[0] = sptr(As[0]); sA[1] = sptr(As[1]); sA[2] = sptr(As[2]);
    sB[0] = sptr(Bs[0]); sB[1] = sptr(Bs[1]); sB[2] = sptr(Bs[2]);

    const int tid = threadIdx.x;
    const int lane = tid % 32;
    const int warp = tid / 32;
    const int gid = lane / 4;
    const int tig = lane % 4;
    const int wm = warp / 4;
    const int wn = warp % 4;
    const int m0 = blockIdx.y * 128;
    const int n0 = blockIdx.x * 128;

    const int arow = wm * 64 + (lane % 16);
    const int ga_add = lane / 16;
    const int brow = wn * 32 + ((lane / 16) % 2) * 8 + (lane % 8);
    const int gb_add = (lane / 8) % 2;

    float acc[4][4][4];
    for (int i = 0; i < 4; i++) {
        for (int j = 0; j < 4; j++) {
            for (int q = 0; q < 4; q++) { acc[i][j][q] = 0.f; }
        }
    }

    gemm_stage(sA[0], sB[0], Ap, Bp, m0, n0, 0, tid);
    cpcommit();
    gemm_stage(sA[1], sB[1], Ap, Bp, m0, n0, 32, tid);
    cpcommit();
    gemm_stage(sA[2], sB[2], Ap, Bp, m0, n0, 64, tid);
    cpcommit();

    for (int kk = 0; kk < 16; kk++) {
        if (kk < 14) { cpwait2(); }
        else if (kk == 14) { cpwait1(); }
        else { cpwait0(); }
        __syncthreads();
        int buf = kk % 3;
        const unsigned cA = sA[buf];
        const unsigned cB = sB[buf];

        for (int ks = 0; ks < 4; ks++) {
            unsigned af[4][4];
            unsigned bf[2][4];
            for (int mt = 0; mt < 4; mt++) {
                int r = arow + mt * 16;
                int grp = (ks * 2 + ga_add) ^ (r % 8);
                ldsm4(af[mt][0], af[mt][1], af[mt][2], af[mt][3], cA + r * 128 + grp * 16);
            }
            for (int p = 0; p < 2; p++) {
                int r = brow + p * 16;
                int grp = (ks * 2 + gb_add) ^ (r % 8);
                ldsm4(bf[p][0], bf[p][1], bf[p][2], bf[p][3], cB + r * 128 + grp * 16);
            }
            for (int mt = 0; mt < 4; mt++) {
                for (int p = 0; p < 2; p++) {
                    mma16(acc[mt][2 * p + 0], af[mt][0], af[mt][1], af[mt][2], af[mt][3],
                          bf[p][0], bf[p][1]);
                    mma16(acc[mt][2 * p + 1], af[mt][0], af[mt][1], af[mt][2], af[mt][3],
                          bf[p][2], bf[p][3]);
                }
            }
        }
        __syncthreads();
        if (kk < 13) {
            gemm_stage(sA[buf], sB[buf], Ap, Bp, m0, n0, (kk + 3) * 32, tid);
            cpcommit();
        }
    }

    for (int mt = 0; mt < 4; mt++) {
        for (int nt = 0; nt < 4; nt++) {
            int row = m0 + wm * 64 + mt * 16 + gid;
            int colu = (n0 + wn * 32 + nt * 8 + 2 * tig) / 2;
            Cp[row * Nu + colu] = pack_h2(acc[mt][nt][0], acc[mt][nt][1]);
            Cp[(row + 8) * Nu + colu] = pack_h2(acc[mt][nt][2], acc[mt][nt][3]);
        }
    }
}

// ---------------------------------------------------------------------------
// GEMM fp32 out + bias (output projection). 3-stage cp.async, 256 threads.
// ---------------------------------------------------------------------------
__global__ __launch_bounds__(256) void gemm_hh_f(
    const unsigned* __restrict__ Ap, const unsigned* __restrict__ Bp,
    float* __restrict__ Cp, const float* __restrict__ bias)
{
    __shared__ unsigned As[3][128 * 32];
    __shared__ unsigned Bs[3][128 * 32];
    unsigned sA[3];
    unsigned sB[3];
    sA[0] = sptr(As[0]); sA[1] = sptr(As[1]); sA[2] = sptr(As[2]);
    sB[0] = sptr(Bs[0]); sB[1] = sptr(Bs[1]); sB[2] = sptr(Bs[2]);

    const int tid = threadIdx.x;
    const int lane = tid % 32;
    const int warp = tid / 32;
    const int gid = lane / 4;
    const int tig = lane % 4;
    const int wm = warp / 4;
    const int wn = warp % 4;
    const int m0 = blockIdx.y * 128;
    const int n0 = blockIdx.x * 128;

    const int arow = wm * 64 + (lane % 16);
    const int ga_add = lane / 16;
    const int brow = wn * 32 + ((lane / 16) % 2) * 8 + (lane % 8);
    const int gb_add = (lane / 8) % 2;

    float acc[4][4][4];
    for (int i = 0; i < 4; i++) {
        for (int j = 0; j < 4; j++) {
            for (int q = 0; q < 4; q++) { acc[i][j][q] = 0.f; }
        }
    }

    gemm_stage(sA[0], sB[0], Ap, Bp, m0, n0, 0, tid);
    cpcommit();
    gemm_stage(sA[1], sB[1], Ap, Bp, m0, n0, 32, tid);
    cpcommit();
    gemm_stage(sA[2], sB[2], Ap, Bp, m0, n0, 64, tid);
    cpcommit();

    for (int kk = 0; kk < 16; kk++) {
        if (kk < 14) { cpwait2(); }
        else if (kk == 14) { cpwait1(); }
        else { cpwait0(); }
        __syncthreads();
        int buf = kk % 3;
        const unsigned cA = sA[buf];
        const unsigned cB = sB[buf];

        for (int ks = 0; ks < 4; ks++) {
            unsigned af[4][4];
            unsigned bf[2][4];
            for (int mt = 0; mt < 4; mt++) {
                int r = arow + mt * 16;
                int grp = (ks * 2 + ga_add) ^ (r % 8);
                ldsm4(af[mt][0], af[mt][1], af[mt][2], af[mt][3], cA + r * 128 + grp * 16);
            }
            for (int p = 0; p < 2; p++) {
                int r = brow + p * 16;
                int grp = (ks * 2 + gb_add) ^ (r % 8);
                ldsm4(bf[p][0], bf[p][1], bf[p][2], bf[p][3], cB + r * 128 + grp * 16);
            }
            for (int mt = 0; mt < 4; mt++) {
                for (int p = 0; p < 2; p++) {
                    mma16(acc[mt][2 * p + 0], af[mt][0], af[mt][1], af[mt][2], af[mt][3],
                          bf[p][0], bf[p][1]);
                    mma16(acc[mt][2 * p + 1], af[mt][0], af[mt][1], af[mt][2], af[mt][3],
                          bf[p][2], bf[p][3]);
                }
            }
        }
        __syncthreads();
        if (kk < 13) {
            gemm_stage(sA[buf], sB[buf], Ap, Bp, m0, n0, (kk + 3) * 32, tid);
            cpcommit();
        }
    }

    for (int mt = 0; mt < 4; mt++) {
        for (int nt = 0; nt < 4; nt++) {
            int row = m0 + wm * 64 + mt * 16 + gid;
            int col = n0 + wn * 32 + nt * 8 + 2 * tig;
            float bb0 = bias[col];
            float bb1 = bias[col + 1];
            *(float2*)(Cp + row * 1024 + col) =
                make_float2(acc[mt][nt][0] + bb0, acc[mt][nt][1] + bb1);
            *(float2*)(Cp + (row + 8) * 1024 + col) =
                make_float2(acc[mt][nt][2] + bb0, acc[mt][nt][3] + bb1);
        }
    }
}

// ---------------------------------------------------------------------------
// Flash attention: Br=128, 4 warps, 2-stage cp.async K/V pipeline.
// Grid (bh=64, qt=16), LONGEST-FIRST: q0 = (15 - blockIdx.y) * 128 so the
// high-work diagonal blocks are scheduled in the first wave.
// qkv buffer: row stride 768u, q at +0, k at +512, v at +640.
// ---------------------------------------------------------------------------
__device__ __forceinline__ void kv_stage(
    unsigned sKb, unsigned sVb, const unsigned* __restrict__ kvrow0, int kt, int tid)
{
    int r = tid / 2;
    int rx = r % 8;
    const unsigned* src = kvrow0 + (kt * 64 + r) * 768;
    for (int j = 0; j < 4; j++) {
        int grp = j * 2 + (tid % 2);
        unsigned sw = (unsigned)((grp ^ rx) * 16);
        cpa16(sKb + r * 128 + sw, src + grp * 4);
        cpa16(sVb + r * 128 + sw, src + 128 + grp * 4);
    }
}

__global__ __launch_bounds__(128) void attn_h(
    const unsigned* __restrict__ qkvbuf, unsigned* __restrict__ obuf)
{
    __shared__ unsigned Qs[128 * 32];
    __shared__ unsigned Ks[2][64 * 32];
    __shared__ unsigned Vs[2][64 * 32];
    const unsigned sQ = sptr(Qs);
    unsigned sK[2];
    unsigned sV[2];
    sK[0] = sptr(Ks[0]); sK[1] = sptr(Ks[1]);
    sV[0] = sptr(Vs[0]); sV[1] = sptr(Vs[1]);

    const int tid = threadIdx.x;
    const int lane = tid % 32;
    const int warp = tid / 32;
    const int gid = lane / 4;
    const int tig = lane % 4;
    const int q0 = (15 - blockIdx.y) * 128;
    const int bh = blockIdx.x;
    const int bb = bh / 16;
    const int hh = bh % 16;
    const int gg = hh / 4;

    const int kmax = q0 / 64 + 1;
    const unsigned* kvrow0 = qkvbuf + (size_t)bb * TT * 768 + 512 + gg * 32;

    kv_stage(sK[0], sV[0], kvrow0, 0, tid);
    cpcommit();
    kv_stage(sK[1], sV[1], kvrow0, 1, tid);
    cpcommit();

    {
        const unsigned* srow = qkvbuf + ((size_t)bb * TT + q0 + tid) * 768 + hh * 32;
        unsigned* drow = Qs + tid * 32;
        int rx = tid % 8;
        for (int grp = 0; grp < 8; grp++) {
            *(uint4*)(drow + (grp ^ rx) * 4) = *(const uint4*)(srow + grp * 4);
        }
    }
    __syncthreads();

    unsigned qf[2][4][4];
    const int qga = lane / 16;
    for (int mt = 0; mt < 2; mt++) {
        int qrow = warp * 32 + mt * 16 + (lane % 16);
        for (int ks = 0; ks < 4; ks++) {
            int grp = (ks * 2 + qga) ^ (qrow % 8);
            ldsm4(qf[mt][ks][0], qf[mt][ks][1], qf[mt][ks][2], qf[mt][ks][3],
                  sQ + qrow * 128 + grp * 16);
        }
    }

    float oacc[2][8][4];
    for (int mt = 0; mt < 2; mt++) {
        for (int nt = 0; nt < 8; nt++) {
            for (int q = 0; q < 4; q++) { oacc[mt][nt][q] = 0.f; }
        }
    }
    float mr[2][2];
    float lr[2][2];
    for (int mt = 0; mt < 2; mt++) {
        mr[mt][0] = -1e30f; mr[mt][1] = -1e30f;
        lr[mt][0] = 0.f; lr[mt][1] = 0.f;
    }

    const int rw0 = q0 + warp * 32;

    const int s_nadd = ((lane / 16) % 2) * 8 + (lane % 8);
    const int s_gadd = (lane / 8) % 2;
    const int v_kadd = ((lane / 8) % 2) * 8 + (lane % 8);
    const int v_gadd = (lane / 16) % 2;

    for (int kt = 0; kt <= kmax; kt++) {
        if (kt < kmax) { cpwait1(); } else { cpwait0(); }
        __syncthreads();
        const unsigned cK = sK[kt % 2];
        const unsigned cV = sV[kt % 2];

        if (kt * 64 <= rw0 + 31) {
            float sc[2][8][4];
            for (int mt = 0; mt < 2; mt++) {
                for (int nt = 0; nt < 8; nt++) {
                    for (int q = 0; q < 4; q++) { sc[mt][nt][q] = 0.f; }
                }
            }
            for (int ks = 0; ks < 4; ks++) {
                for (int p = 0; p < 4; p++) {
                    int nrow = p * 16 + s_nadd;
                    int grp = (ks * 2 + s_gadd) ^ (nrow % 8);
                    unsigned kf0, kf1, kf2, kf3;
                    ldsm4(kf0, kf1, kf2, kf3, cK + nrow * 128 + grp * 16);
                    for (int mt = 0; mt < 2; mt++) {
                        mma16(sc[mt][2 * p + 0], qf[mt][ks][0], qf[mt][ks][1], qf[mt][ks][2], qf[mt][ks][3], kf0, kf1);
                        mma16(sc[mt][2 * p + 1], qf[mt][ks][0], qf[mt][ks][1], qf[mt][ks][2], qf[mt][ks][3], kf2, kf3);
                    }
                }
            }

            if (kt * 64 + 63 > rw0) {
                for (int mt = 0; mt < 2; mt++) {
                    int rowA = rw0 + mt * 16 + gid;
                    int rowB = rowA + 8;
                    for (int nt = 0; nt < 8; nt++) {
                        int kcol = kt * 64 + nt * 8 + 2 * tig;
                        if (kcol > rowA) { sc[mt][nt][0] = -1e30f; }
                        if (kcol + 1 > rowA) { sc[mt][nt][1] = -1e30f; }
                        if (kcol > rowB) { sc[mt][nt][2] = -1e30f; }
                        if (kcol + 1 > rowB) { sc[mt][nt][3] = -1e30f; }
                    }
                }
            }

            for (int mt = 0; mt < 2; mt++) {
                float mt0 = -1e30f;
                float mt1 = -1e30f;
                for (int nt = 0; nt < 8; nt++) {
                    mt0 = fmaxf(mt0, fmaxf(sc[mt][nt][0], sc[mt][nt][1]));
                    mt1 = fmaxf(mt1, fmaxf(sc[mt][nt][2], sc[mt][nt][3]));
                }
                mt0 = fmaxf(mt0, __shfl_xor_sync(0xffffffffu, mt0, 1));
                mt0 = fmaxf(mt0, __shfl_xor_sync(0xffffffffu, mt0, 2));
                mt1 = fmaxf(mt1, __shfl_xor_sync(0xffffffffu, mt1, 1));
                mt1 = fmaxf(mt1, __shfl_xor_sync(0xffffffffu, mt1, 2));
                float mn0 = fmaxf(mr[mt][0], mt0);
                float mn1 = fmaxf(mr[mt][1], mt1);
                float c0 = __expf(mr[mt][0] - mn0);
                float c1 = __expf(mr[mt][1] - mn1);
                float ps0 = 0.f;
                float ps1 = 0.f;
                for (int nt = 0; nt < 8; nt++) {
                    sc[mt][nt][0] = __expf(sc[mt][nt][0] - mn0);
                    sc[mt][nt][1] = __expf(sc[mt][nt][1] - mn0);
                    sc[mt][nt][2] = __expf(sc[mt][nt][2] - mn1);
                    sc[mt][nt][3] = __expf(sc[mt][nt][3] - mn1);
                    ps0 += sc[mt][nt][0] + sc[mt][nt][1];
                    ps1 += sc[mt][nt][2] + sc[mt][nt][3];
                    oacc[mt][nt][0] *= c0;
                    oacc[mt][nt][1] *= c0;
                    oacc[mt][nt][2] *= c1;
                    oacc[mt][nt][3] *= c1;
                }
                ps0 += __shfl_xor_sync(0xffffffffu, ps0, 1);
                ps0 += __shfl_xor_sync(0xffffffffu, ps0, 2);
                ps1 += __shfl_xor_sync(0xffffffffu, ps1, 1);
                ps1 += __shfl_xor_sync(0xffffffffu, ps1, 2);
                lr[mt][0] = lr[mt][0] * c0 + ps0;
                lr[mt][1] = lr[mt][1] * c1 + ps1;
                mr[mt][0] = mn0;
                mr[mt][1] = mn1;
            }

            for (int ks = 0; ks < 4; ks++) {
                unsigned pf[2][4];
                for (int mt = 0; mt < 2; mt++) {
                    pf[mt][0] = pack_h2(sc[mt][2 * ks + 0][0], sc[mt][2 * ks + 0][1]);
                    pf[mt][1] = pack_h2(sc[mt][2 * ks + 0][2], sc[mt][2 * ks + 0][3]);
                    pf[mt][2] = pack_h2(sc[mt][2 * ks + 1][0], sc[mt][2 * ks + 1][1]);
                    pf[mt][3] = pack_h2(sc[mt][2 * ks + 1][2], sc[mt][2 * ks + 1][3]);
                }
                for (int p = 0; p < 4; p++) {
                    int krow = ks * 16 + v_kadd;
                    int grp = (p * 2 + v_gadd) ^ (krow % 8);
                    unsigned vf0, vf1, vf2, vf3;
                    ldsm4t(vf0, vf1, vf2, vf3, cV + krow * 128 + grp * 16);
                    for (int mt = 0; mt < 2; mt++) {
                        mma16(oacc[mt][2 * p + 0], pf[mt][0], pf[mt][1], pf[mt][2], pf[mt][3], vf0, vf1);
                        mma16(oacc[mt][2 * p + 1], pf[mt][0], pf[mt][1], pf[mt][2], pf[mt][3], vf2, vf3);
                    }
                }
            }
        }

        __syncthreads();
        if (kt + 2 <= kmax) {
            kv_stage(sK[kt % 2], sV[kt % 2], kvrow0, kt + 2, tid);
            cpcommit();
        }
    }

    for (int mt = 0; mt < 2; mt++) {
        float i0 = 1.f / lr[mt][0];
        float i1 = 1.f / lr[mt][1];
        int rowA = rw0 + mt * 16 + gid;
        int rowB = rowA + 8;
        for (int nt = 0; nt < 8; nt++) {
            int colu = hh * 32 + nt * 4 + tig;
            obuf[((size_t)bb * TT + rowA) * 512 + colu] = pack_h2(oacc[mt][nt][0] * i0, oacc[mt][nt][1] * i0);
            obuf[((size_t)bb * TT + rowB) * 512 + colu] = pack_h2(oacc[mt][nt][2] * i1, oacc[mt][nt][3] * i1);
        }
    }
}

extern "C" void kernel_launch(void* const* d_in, const int* in_sizes, int n_in,
                              void* d_out, int out_size)
{
    const float* x  = (const float*)d_in[0];
    const float* Wq = (const float*)d_in[1];
    const float* Wk = (const float*)d_in[2];
    const float* Wv = (const float*)d_in[3];
    const float* Wp = (const float*)d_in[4];
    const float* bp = (const float*)d_in[5];
    float* out = (float*)d_out;

    unsigned* gx = 0;
    unsigned* gwqkv = 0;
    unsigned* gwp = 0;
    unsigned* gqkv = 0;
    unsigned* ga = 0;
    cudaGetSymbolAddress((void**)&gx, g_x);
    cudaGetSymbolAddress((void**)&gwqkv, g_wqkv);
    cudaGetSymbolAddress((void**)&gwp, g_wp);
    cudaGetSymbolAddress((void**)&gqkv, g_qkv);
    cudaGetSymbolAddress((void**)&ga, g_attn);

    conv_all<<<10752, 256>>>(x, Wq, Wk, Wv, Wp, gx, gwqkv, gwp);

    gemm_hh_h<<<dim3(12, 64), 256>>>(gx, gwqkv, gqkv, 768);

    attn_h<<<dim3(64, 16), 128>>>(gqkv, ga);

    gemm_hh_f<<<dim3(8, 64), 256>>>(ga, gwp, out, bp);
}